// round 4
// baseline (speedup 1.0000x reference)
#include <cuda_runtime.h>
#include <cuda_bf16.h>
#include <math.h>

// Problem constants
#define BB   2
#define LL   2048
#define HID  2048
#define HH   16
#define DD   128
#define MM   (BB*LL)          // 4096
#define CHK  64               // scan chunk length
#define DV   32               // v-dim split per scan block
#define NSPLIT 4              // 128 / DV

// ---------------- device scratch (no cudaMalloc allowed) ----------------
__device__ float g_raw [MM*HID];     // raw GEMM output (reused q/k/v)
__device__ float g_q   [MM*HID];     // phi_q, layout [b*H+h][t][d]
__device__ float g_k   [MM*HID];     // phi_k, layout [b*H+h][t][d]
__device__ float g_v   [MM*HID];     // v,     layout [b*H+h][t][d]
__device__ float g_y   [MM*HID];     // scan output, layout [b*L+t][HID]
__device__ float g_beta[BB*HH*LL];   // [b*H+h][t]

// =====================================================================
// SGEMM: C[M,N] = A[M,K] @ B[K,N] (+ bias[N]); 128x128 tile, BK=8,
// 256 threads, 8x8 microtile, double-buffered smem.
// =====================================================================
__global__ __launch_bounds__(256) void sgemm_kernel(
    const float* __restrict__ A, const float* __restrict__ Bm,
    const float* __restrict__ bias, float* __restrict__ Cm,
    int M, int N, int K)
{
    __shared__ float As[2][8][128];
    __shared__ float Bs[2][8][128];

    const int tid = threadIdx.x;
    const int ar  = tid >> 1;          // 0..127
    const int ac  = (tid & 1) << 2;    // 0 or 4
    const int brr = tid >> 5;          // 0..7
    const int bcc = (tid & 31) << 2;   // 0..124
    const int tr  = tid >> 4;          // 0..15
    const int tc  = tid & 15;          // 0..15

    const float* Ap = A  + (size_t)(blockIdx.y * 128 + ar) * K + ac;
    const float* Bp = Bm + (size_t)brr * N + blockIdx.x * 128 + bcc;

    float4 pa = *(const float4*)Ap;
    float4 pb = *(const float4*)Bp;
    As[0][ac+0][ar]=pa.x; As[0][ac+1][ar]=pa.y; As[0][ac+2][ar]=pa.z; As[0][ac+3][ar]=pa.w;
    *(float4*)&Bs[0][brr][bcc] = pb;
    __syncthreads();

    float acc[8][8];
    #pragma unroll
    for (int i=0;i<8;i++)
        #pragma unroll
        for (int j=0;j<8;j++) acc[i][j]=0.f;

    const int KT = K >> 3;
    int buf = 0;
    for (int kt = 0; kt < KT; kt++) {
        if (kt + 1 < KT) {
            pa = *(const float4*)(Ap + (kt+1)*8);
            pb = *(const float4*)(Bp + (size_t)(kt+1)*8*N);
        }
        #pragma unroll
        for (int k = 0; k < 8; k++) {
            float ra[8], rb[8];
            *(float4*)&ra[0] = *(float4*)&As[buf][k][tr*8];
            *(float4*)&ra[4] = *(float4*)&As[buf][k][tr*8+4];
            *(float4*)&rb[0] = *(float4*)&Bs[buf][k][tc*8];
            *(float4*)&rb[4] = *(float4*)&Bs[buf][k][tc*8+4];
            #pragma unroll
            for (int i=0;i<8;i++)
                #pragma unroll
                for (int j=0;j<8;j++)
                    acc[i][j] = fmaf(ra[i], rb[j], acc[i][j]);
        }
        if (kt + 1 < KT) {
            buf ^= 1;
            As[buf][ac+0][ar]=pa.x; As[buf][ac+1][ar]=pa.y;
            As[buf][ac+2][ar]=pa.z; As[buf][ac+3][ar]=pa.w;
            *(float4*)&Bs[buf][brr][bcc] = pb;
            __syncthreads();
        }
    }

    float bvals[8];
    #pragma unroll
    for (int j=0;j<8;j++)
        bvals[j] = bias ? bias[blockIdx.x*128 + tc*8 + j] : 0.f;

    float* Cp = Cm + (size_t)(blockIdx.y*128 + tr*8) * N + blockIdx.x*128 + tc*8;
    #pragma unroll
    for (int i=0;i<8;i++) {
        float4 v0, v1;
        v0.x=acc[i][0]+bvals[0]; v0.y=acc[i][1]+bvals[1];
        v0.z=acc[i][2]+bvals[2]; v0.w=acc[i][3]+bvals[3];
        v1.x=acc[i][4]+bvals[4]; v1.y=acc[i][5]+bvals[5];
        v1.z=acc[i][6]+bvals[6]; v1.w=acc[i][7]+bvals[7];
        *(float4*)(Cp + (size_t)i*N)     = v0;
        *(float4*)(Cp + (size_t)i*N + 4) = v1;
    }
}

// =====================================================================
// RoPE + elu+1 + head-major transpose (apply=1), or plain transpose (apply=0)
// in:  [b*L+t][HID] (GEMM output)    out: [(b*H+h)*L + t][D]
// =====================================================================
__global__ __launch_bounds__(256) void rope_phi_kernel(
    const float* __restrict__ in, float* __restrict__ out, int apply)
{
    const int m = blockIdx.x;           // 0..MM-1
    const int b = m >> 11;              // /L
    const int t = m & (LL-1);
    if (apply) {
        for (int p = threadIdx.x; p < HH*64; p += blockDim.x) {
            const int h = p >> 6, j = p & 63;
            float xe = in[(size_t)m*HID + h*DD + j];
            float xo = in[(size_t)m*HID + h*DD + 64 + j];
            // inv_freq = 10000^(-j/64): exact in double, rounded to fp32 like jax
            float invf = (float)exp(-(double)j * 9.210340371976184 / 64.0);
            float ang  = (float)t * invf;          // fp32 product like jax
            double sd, cd; sincos((double)ang, &sd, &cd);
            float c = (float)cd, s = (float)sd;
            float oe = xe*c - xo*s;
            float oo = xe*s + xo*c;
            oe = (oe > 0.f) ? (oe + 1.f) : expf(oe);   // elu(x)+1
            oo = (oo > 0.f) ? (oo + 1.f) : expf(oo);
            size_t base = ((size_t)(b*HH + h)*LL + t)*DD;
            out[base + j]      = oe;
            out[base + 64 + j] = oo;
        }
    } else {
        for (int p = threadIdx.x; p < HID; p += blockDim.x) {
            const int h = p >> 7, d = p & 127;
            out[((size_t)(b*HH + h)*LL + t)*DD + d] = in[(size_t)m*HID + p];
        }
    }
}

// =====================================================================
// beta = clip(sigmoid(x @ Wg + bg), 0.8, 0.9995), stored [b*H+h][t]
// one block per token row, one warp per head.
// =====================================================================
__global__ __launch_bounds__(512) void beta_kernel(
    const float* __restrict__ x, const float* __restrict__ Wg,
    const float* __restrict__ bg, float* __restrict__ beta)
{
    __shared__ float row[HID];
    const int m = blockIdx.x;
    for (int i = threadIdx.x; i < HID; i += 512) row[i] = x[(size_t)m*HID + i];
    __syncthreads();
    const int w = threadIdx.x >> 5, lane = threadIdx.x & 31;   // w = head
    float s = 0.f;
    for (int d = lane; d < HID; d += 32) s = fmaf(row[d], Wg[d*HH + w], s);
    #pragma unroll
    for (int o = 16; o; o >>= 1) s += __shfl_xor_sync(0xffffffffu, s, o);
    if (lane == 0) {
        s += bg[w];
        float bt = 1.f / (1.f + expf(-s));
        bt = fminf(fmaxf(bt, 0.8f), 0.9995f);
        const int b = m >> 11, t = m & (LL-1);
        beta[(size_t)(b*HH + w)*LL + t] = bt;
    }
}

// =====================================================================
// Chunked decayed-linear-attention scan.
// grid = B*H*NSPLIT (=128) blocks, 256 threads, dynamic smem.
// Each block: one (b,h) pair, one DV=32 slice of the v/output dims.
// Per chunk (C=64):
//   A[i][s] = (q_i.k_s) * exp(Lc_i - Lc_s), masked s<=i      (64x64x128 GEMM)
//   y = (A@V + eLc_i * q_i@S) / (rowsum(A) + eLc_i*(q_i.z) + EPS)
//   S = eLc_{C-1}*S + (exp(Lc_{C-1}-Lc_s) k_s)^T V ;  z likewise
// =====================================================================
__global__ __launch_bounds__(256) void scan_kernel(
    const float* __restrict__ gq, const float* __restrict__ gk,
    const float* __restrict__ gv, const float* __restrict__ gbeta,
    float* __restrict__ gy)
{
    extern __shared__ float sm[];
    float* Qt  = sm;                 // [128][68]  Q^T (d-major)
    float* Kt  = Qt  + 128*68;       // [128][68]  K^T
    float* Vs  = Kt  + 128*68;       // [64][36]
    float* At  = Vs  + 64*36;        // [64][68]   A^T (s-major), decayed+masked
    float* Ssm = At  + 64*68;        // [128][36]  state S[d][e]
    float* z   = Ssm + 128*36;       // [128]
    float* Lc  = z   + 128;          // [64] cumulative log-beta
    float* eLc = Lc  + 64;           // [64] exp(Lc)
    float* ksc = eLc + 64;           // [64] exp(Lc[C-1]-Lc[s])
    float* rsum= ksc + 64;           // [64]
    float* qz  = rsum+ 64;           // [64]
    float* bl  = qz  + 64;           // [64] log-beta

    const int tid   = threadIdx.x;
    const int bh    = blockIdx.x / NSPLIT;
    const int split = blockIdx.x % NSPLIT;
    const int b = bh >> 4, h = bh & 15;

    const float* qp = gq + (size_t)bh*LL*DD;
    const float* kp = gk + (size_t)bh*LL*DD;
    const float* vp = gv + (size_t)bh*LL*DD + split*DV;
    const float* bp = gbeta + (size_t)bh*LL;
    float*       yp = gy + (size_t)b*LL*HID + h*DD + split*DV;

    // thread roles
    const int txA = tid & 15, tyA = tid >> 4;   // A-gemm: 4x4 at (tyA*4, txA*4)
    const int txO = tid & 7,  tyO = tid >> 3;   // O: rows {2tyO,2tyO+1}, cols 4txO
                                                // SU: rows 4tyO, cols 4txO
    // init state
    for (int i = tid; i < 128*36; i += 256) Ssm[i] = 0.f;
    if (tid < 128) z[tid] = 0.f;

    for (int ch = 0; ch < LL/CHK; ch++) {
        const int t0 = ch * CHK;
        __syncthreads();                         // smem safe to overwrite
        // ---- load Q,K (transposed), V, log-beta ----
        for (int idx = tid; idx < CHK*128; idx += 256) {
            const int i = idx >> 7, d = idx & 127;
            Qt[d*68 + i] = qp[(size_t)(t0+i)*DD + d];
            Kt[d*68 + i] = kp[(size_t)(t0+i)*DD + d];
        }
        for (int idx = tid; idx < CHK*DV; idx += 256) {
            const int i = idx >> 5, e = idx & 31;
            Vs[i*36 + e] = vp[(size_t)(t0+i)*DD + e];
        }
        if (tid < CHK) bl[tid] = logf(bp[t0+tid]);
        __syncthreads();
        if (tid == 0) {                          // serial cumsum (cheap)
            float a = 0.f;
            for (int i = 0; i < CHK; i++) { a += bl[i]; Lc[i] = a; }
        }
        __syncthreads();

        // ---- A = Q K^T  (64x64, k=128) ----
        float accA[4][4];
        #pragma unroll
        for (int i=0;i<4;i++) { accA[i][0]=0;accA[i][1]=0;accA[i][2]=0;accA[i][3]=0; }
        for (int k = 0; k < 128; k++) {
            float4 qa = *(float4*)&Qt[k*68 + (tyA<<2)];
            float4 kb = *(float4*)&Kt[k*68 + (txA<<2)];
            const float qv[4] = {qa.x,qa.y,qa.z,qa.w};
            const float kv[4] = {kb.x,kb.y,kb.z,kb.w};
            #pragma unroll
            for (int i=0;i<4;i++)
                #pragma unroll
                for (int s=0;s<4;s++)
                    accA[i][s] = fmaf(qv[i], kv[s], accA[i][s]);
        }
        // per-row helpers (Lc ready; z is pre-update)
        if (tid < CHK) {
            const int i = tid;
            eLc[i] = expf(Lc[i]);
            ksc[i] = expf(Lc[CHK-1] - Lc[i]);
            float s = 0.f;
            for (int d = 0; d < 128; d++) s = fmaf(Qt[d*68 + i], z[d], s);
            qz[i] = s;
        }
        // decay + causal mask, store A^T
        #pragma unroll
        for (int ii=0; ii<4; ii++) {
            const int i = (tyA<<2) + ii;
            #pragma unroll
            for (int ss=0; ss<4; ss++) {
                const int s = (txA<<2) + ss;
                At[s*68 + i] = (s <= i) ? accA[ii][ss]*expf(Lc[i]-Lc[s]) : 0.f;
            }
        }
        __syncthreads();
        if (tid < CHK) {
            float s = 0.f;
            for (int sI = 0; sI < CHK; sI++) s += At[sI*68 + tid];
            rsum[tid] = s;
        }
        __syncthreads();

        // ---- output: O = A@V + eLc * Q@S ; y = O/denom ----
        float oA[2][4] = {{0,0,0,0},{0,0,0,0}};
        float oI[2][4] = {{0,0,0,0},{0,0,0,0}};
        for (int s = 0; s < CHK; s++) {
            const float a0 = At[s*68 + (tyO<<1)];
            const float a1 = At[s*68 + (tyO<<1) + 1];
            const float4 v4 = *(float4*)&Vs[s*36 + (txO<<2)];
            oA[0][0]=fmaf(a0,v4.x,oA[0][0]); oA[0][1]=fmaf(a0,v4.y,oA[0][1]);
            oA[0][2]=fmaf(a0,v4.z,oA[0][2]); oA[0][3]=fmaf(a0,v4.w,oA[0][3]);
            oA[1][0]=fmaf(a1,v4.x,oA[1][0]); oA[1][1]=fmaf(a1,v4.y,oA[1][1]);
            oA[1][2]=fmaf(a1,v4.z,oA[1][2]); oA[1][3]=fmaf(a1,v4.w,oA[1][3]);
        }
        for (int d = 0; d < 128; d++) {
            const float q0 = Qt[d*68 + (tyO<<1)];
            const float q1 = Qt[d*68 + (tyO<<1) + 1];
            const float4 s4 = *(float4*)&Ssm[d*36 + (txO<<2)];
            oI[0][0]=fmaf(q0,s4.x,oI[0][0]); oI[0][1]=fmaf(q0,s4.y,oI[0][1]);
            oI[0][2]=fmaf(q0,s4.z,oI[0][2]); oI[0][3]=fmaf(q0,s4.w,oI[0][3]);
            oI[1][0]=fmaf(q1,s4.x,oI[1][0]); oI[1][1]=fmaf(q1,s4.y,oI[1][1]);
            oI[1][2]=fmaf(q1,s4.z,oI[1][2]); oI[1][3]=fmaf(q1,s4.w,oI[1][3]);
        }
        #pragma unroll
        for (int r=0; r<2; r++) {
            const int i = (tyO<<1) + r;
            const float g = eLc[i];
            const float inv = 1.f / (rsum[i] + g*qz[i] + 1e-6f);
            float4 o;
            o.x = (oA[r][0] + g*oI[r][0]) * inv;
            o.y = (oA[r][1] + g*oI[r][1]) * inv;
            o.z = (oA[r][2] + g*oI[r][2]) * inv;
            o.w = (oA[r][3] + g*oI[r][3]) * inv;
            *(float4*)&yp[(size_t)(t0+i)*HID + (txO<<2)] = o;
        }
        __syncthreads();                         // all reads of S,z,At done

        // ---- state update ----
        const float G = eLc[CHK-1];
        {
            float accS[4][4];
            #pragma unroll
            for (int i=0;i<4;i++){accS[i][0]=0;accS[i][1]=0;accS[i][2]=0;accS[i][3]=0;}
            const int d0 = tyO << 2;
            for (int s = 0; s < CHK; s++) {
                const float sc = ksc[s];
                const float4 v4 = *(float4*)&Vs[s*36 + (txO<<2)];
                float kk[4];
                #pragma unroll
                for (int dd=0; dd<4; dd++) kk[dd] = Kt[(d0+dd)*68 + s] * sc;
                #pragma unroll
                for (int dd=0; dd<4; dd++) {
                    accS[dd][0]=fmaf(kk[dd],v4.x,accS[dd][0]);
                    accS[dd][1]=fmaf(kk[dd],v4.y,accS[dd][1]);
                    accS[dd][2]=fmaf(kk[dd],v4.z,accS[dd][2]);
                    accS[dd][3]=fmaf(kk[dd],v4.w,accS[dd][3]);
                }
            }
            #pragma unroll
            for (int dd=0; dd<4; dd++) {
                float4 sv = *(float4*)&Ssm[(d0+dd)*36 + (txO<<2)];
                sv.x = fmaf(G, sv.x, accS[dd][0]);
                sv.y = fmaf(G, sv.y, accS[dd][1]);
                sv.z = fmaf(G, sv.z, accS[dd][2]);
                sv.w = fmaf(G, sv.w, accS[dd][3]);
                *(float4*)&Ssm[(d0+dd)*36 + (txO<<2)] = sv;
            }
        }
        if (tid < 128) {
            float zv = z[tid] * G;
            for (int s = 0; s < CHK; s++) zv = fmaf(Kt[tid*68 + s], ksc[s], zv);
            z[tid] = zv;
        }
    }
}

// =====================================================================
// launch
// =====================================================================
#define SCAN_SMEM ((128*68*2 + 64*36 + 64*68 + 128*36 + 128 + 6*64) * 4)

extern "C" void kernel_launch(void* const* d_in, const int* in_sizes, int n_in,
                              void* d_out, int out_size)
{
    const float* x  = (const float*)d_in[0];
    const float* Wq = (const float*)d_in[1];
    const float* Wk = (const float*)d_in[2];
    const float* Wv = (const float*)d_in[3];
    const float* Wg = (const float*)d_in[4];
    const float* bg = (const float*)d_in[5];
    const float* Wo = (const float*)d_in[6];
    const float* bo = (const float*)d_in[7];
    float* out = (float*)d_out;

    float *raw, *q, *k, *v, *y, *beta;
    cudaGetSymbolAddress((void**)&raw,  g_raw);
    cudaGetSymbolAddress((void**)&q,    g_q);
    cudaGetSymbolAddress((void**)&k,    g_k);
    cudaGetSymbolAddress((void**)&v,    g_v);
    cudaGetSymbolAddress((void**)&y,    g_y);
    cudaGetSymbolAddress((void**)&beta, g_beta);

    cudaFuncSetAttribute(scan_kernel,
        cudaFuncAttributeMaxDynamicSharedMemorySize, SCAN_SMEM);

    const dim3 ggrid(HID/128, MM/128);   // (16, 32)

    sgemm_kernel<<<ggrid, 256>>>(x, Wq, nullptr, raw, MM, HID, HID);
    rope_phi_kernel<<<MM, 256>>>(raw, q, 1);
    sgemm_kernel<<<ggrid, 256>>>(x, Wk, nullptr, raw, MM, HID, HID);
    rope_phi_kernel<<<MM, 256>>>(raw, k, 1);
    sgemm_kernel<<<ggrid, 256>>>(x, Wv, nullptr, raw, MM, HID, HID);
    rope_phi_kernel<<<MM, 256>>>(raw, v, 0);
    beta_kernel<<<MM, 512>>>(x, Wg, bg, beta);

    scan_kernel<<<BB*HH*NSPLIT, 256, SCAN_SMEM>>>(q, k, v, beta, y);

    sgemm_kernel<<<ggrid, 256>>>(y, Wo, bo, out, MM, HID, HID);
}

// round 7
// speedup vs baseline: 2.5029x; 2.5029x over previous
#include <cuda_runtime.h>
#include <cuda_bf16.h>
#include <math.h>
#include <stdint.h>

// Problem constants
#define BB   2
#define LL   2048
#define HID  2048
#define HH   16
#define DD   128
#define MM   (BB*LL)          // 4096
#define CHK  64               // scan chunk length
#define DV   32               // v-dim split per scan block
#define NSPLIT 4              // 128 / DV

// ---------------- device scratch (no cudaMalloc allowed) ----------------
__device__ __align__(256) float g_raw [MM*HID];     // GEMM fp32 output (reused)
__device__ __align__(256) float g_q   [MM*HID];     // phi_q [b*H+h][t][d]
__device__ __align__(256) float g_k   [MM*HID];     // phi_k
__device__ __align__(256) float g_v   [MM*HID];     // v
__device__ __align__(256) float g_y   [MM*HID];     // scan out [b*L+t][HID]
__device__ __align__(256) float g_beta[BB*HH*LL];   // [b*H+h][t]

// bf16 split buffers
__device__ __align__(256) __nv_bfloat16 g_ahi[MM*HID];       // x or y, hi
__device__ __align__(256) __nv_bfloat16 g_alo[MM*HID];       // x or y, lo
__device__ __align__(256) __nv_bfloat16 g_whi[4*HID*HID];    // W^T hi (q,k,v,o)
__device__ __align__(256) __nv_bfloat16 g_wlo[4*HID*HID];    // W^T lo

// rope tables
__device__ float g_cos[LL*64];
__device__ float g_sin[LL*64];

// =====================================================================
// sm_80-era primitives (legal on plain sm_103 ptxas target)
// =====================================================================
__device__ __forceinline__ uint32_t smem_u32(const void* p) {
    uint32_t a;
    asm("{ .reg .u64 t; cvta.to.shared.u64 t, %1; cvt.u32.u64 %0, t; }"
        : "=r"(a) : "l"(p));
    return a;
}
__device__ __forceinline__ void ldsm_x4(uint32_t addr, uint32_t& r0, uint32_t& r1,
                                        uint32_t& r2, uint32_t& r3) {
    asm volatile("ldmatrix.sync.aligned.m8n8.x4.shared.b16 {%0,%1,%2,%3}, [%4];"
        : "=r"(r0), "=r"(r1), "=r"(r2), "=r"(r3) : "r"(addr));
}
__device__ __forceinline__ void mma_bf16(float* c, const uint32_t* a, const uint32_t* b) {
    asm volatile(
        "mma.sync.aligned.m16n8k16.row.col.f32.bf16.bf16.f32 "
        "{%0,%1,%2,%3}, {%4,%5,%6,%7}, {%8,%9}, {%0,%1,%2,%3};"
        : "+f"(c[0]), "+f"(c[1]), "+f"(c[2]), "+f"(c[3])
        : "r"(a[0]), "r"(a[1]), "r"(a[2]), "r"(a[3]), "r"(b[0]), "r"(b[1]));
}
#define CP_ASYNC16(dst, src) \
    asm volatile("cp.async.cg.shared.global [%0], [%1], 16;" :: "r"(dst), "l"(src))
#define CP_COMMIT() asm volatile("cp.async.commit_group;" ::: "memory")
#define CP_WAIT(n)  asm volatile("cp.async.wait_group %0;" :: "n"(n) : "memory")

// =====================================================================
// bf16 split conversion: hi = bf16(x), lo = bf16(x - hi)
// =====================================================================
__global__ __launch_bounds__(256) void cvt_split_kernel(
    const float4* __restrict__ in, __nv_bfloat16* __restrict__ hi,
    __nv_bfloat16* __restrict__ lo, int n4)
{
    int i = blockIdx.x * 256 + threadIdx.x;
    if (i >= n4) return;
    float4 v = in[i];
    float a[4] = {v.x, v.y, v.z, v.w};
    __nv_bfloat16 hb[4], lb[4];
    #pragma unroll
    for (int j = 0; j < 4; j++) {
        hb[j] = __float2bfloat16(a[j]);
        lb[j] = __float2bfloat16(a[j] - __bfloat162float(hb[j]));
    }
    __nv_bfloat162 h0, h1, l0, l1;
    h0.x = hb[0]; h0.y = hb[1]; h1.x = hb[2]; h1.y = hb[3];
    l0.x = lb[0]; l0.y = lb[1]; l1.x = lb[2]; l1.y = lb[3];
    *(__nv_bfloat162*)(hi + 4*(size_t)i)     = h0;
    *(__nv_bfloat162*)(hi + 4*(size_t)i + 2) = h1;
    *(__nv_bfloat162*)(lo + 4*(size_t)i)     = l0;
    *(__nv_bfloat162*)(lo + 4*(size_t)i + 2) = l1;
}

// W [K=HID][N=HID] fp32 -> W^T hi/lo bf16 [N][K]
__global__ __launch_bounds__(256) void cvt_w_kernel(
    const float* __restrict__ W, __nv_bfloat16* __restrict__ th,
    __nv_bfloat16* __restrict__ tl)
{
    __shared__ float t[32][33];
    const int k0 = blockIdx.y * 32, n0 = blockIdx.x * 32;
    const int tx = threadIdx.x, ty = threadIdx.y;   // block (32,8)
    for (int i = ty; i < 32; i += 8)
        t[i][tx] = W[(size_t)(k0 + i) * HID + n0 + tx];
    __syncthreads();
    for (int i = ty; i < 32; i += 8) {
        float x = t[tx][i];                    // W[k0+tx][n0+i]
        __nv_bfloat16 h = __float2bfloat16(x);
        __nv_bfloat16 l = __float2bfloat16(x - __bfloat162float(h));
        size_t o = (size_t)(n0 + i) * HID + k0 + tx;
        th[o] = h; tl[o] = l;
    }
}

// =====================================================================
// mma.sync GEMM: C[M,N] = A[M,K] @ W[K,N] (+bias), bf16 hi/lo split.
// A as Ah/Al [M][K]; W transposed as Bh/Bl [N][K] (= col-major B).
// 128x128 CTA tile, 8 warps (2x4), 64x32 warp tile, K-stage 64,
// cp.async double-buffered, xor-swizzled smem for ldmatrix.
// =====================================================================
#define GEMM_SMEM (2 * 4 * 16384)   // 2 stages x (Ah,Al,Bh,Bl) x 16KB = 128KB

__global__ __launch_bounds__(256, 1) void gemm_tc_kernel(
    const __nv_bfloat16* __restrict__ Ah, const __nv_bfloat16* __restrict__ Al,
    const __nv_bfloat16* __restrict__ Bh, const __nv_bfloat16* __restrict__ Bl,
    const float* __restrict__ bias, float* __restrict__ C,
    int M, int N, int K)
{
    extern __shared__ __align__(1024) char smem[];
    const uint32_t sbase = smem_u32(smem);

    const int tid  = threadIdx.x;
    const int wid  = tid >> 5, lane = tid & 31;
    const int wm   = wid >> 2, wn = wid & 3;       // warp grid 2x4
    const int m0   = blockIdx.y * 128, n0 = blockIdx.x * 128;

    const __nv_bfloat16* gsrc[4] = {Ah, Al, Bh, Bl};
    const int NS = K >> 6;                          // K/64 stages

    // ---- cp.async one K-stage into buffer buf (0/1) ----
    auto load_stage = [&](int buf, int k0e) {
        const uint32_t bs = sbase + buf * 65536;
        #pragma unroll
        for (int p = 0; p < 16; p++) {
            int idx = tid + p * 256;               // 0..4095
            int j   = idx >> 10;                   // tile 0..3
            int i   = idx & 1023;
            int r   = i >> 3, ch = i & 7;
            int phys = ch ^ (r & 7);
            uint32_t dst = bs + j * 16384 + r * 128 + phys * 16;
            int grow = (j < 2 ? m0 : n0) + r;
            const __nv_bfloat16* src = gsrc[j] + (size_t)grow * K + k0e + ch * 8;
            CP_ASYNC16(dst, src);
        }
        CP_COMMIT();
    };

    // per-lane ldmatrix address components
    const int lw  = lane & 7;
    const int gA  = (lane >> 4) & 1;               // A: k-half select
    const int gB  = (lane >> 3) & 1;               // B: k-half select
    uint32_t offA[4], offB[2];
    #pragma unroll
    for (int mi = 0; mi < 4; mi++)
        offA[mi] = (uint32_t)(wm * 64 + mi * 16 + (lane & 15)) * 128;
    #pragma unroll
    for (int p = 0; p < 2; p++)
        offB[p] = (uint32_t)(wn * 32 + p * 16 + ((lane >> 4) & 1) * 8 + lw) * 128;

    float acc[4][4][4];
    #pragma unroll
    for (int mi = 0; mi < 4; mi++)
        #pragma unroll
        for (int ni = 0; ni < 4; ni++) {
            acc[mi][ni][0] = 0.f; acc[mi][ni][1] = 0.f;
            acc[mi][ni][2] = 0.f; acc[mi][ni][3] = 0.f;
        }

    load_stage(0, 0);

    for (int s = 0; s < NS; s++) {
        if (s + 1 < NS) load_stage((s + 1) & 1, (s + 1) * 64);
        if (s + 1 < NS) { CP_WAIT(1); } else { CP_WAIT(0); }
        __syncthreads();

        const uint32_t stage = sbase + (s & 1) * 65536;
        #pragma unroll
        for (int kk = 0; kk < 4; kk++) {
            const uint32_t swA = (uint32_t)(((kk * 2 + gA) ^ lw) << 4);
            const uint32_t swB = (uint32_t)(((kk * 2 + gB) ^ lw) << 4);
            uint32_t ah[4][4], al[4][4];
            #pragma unroll
            for (int mi = 0; mi < 4; mi++) {
                uint32_t aA = stage + offA[mi] + swA;
                ldsm_x4(aA,          ah[mi][0], ah[mi][1], ah[mi][2], ah[mi][3]);
                ldsm_x4(aA + 16384,  al[mi][0], al[mi][1], al[mi][2], al[mi][3]);
            }
            uint32_t bh[4][2], bl[4][2];
            #pragma unroll
            for (int p = 0; p < 2; p++) {
                uint32_t aB = stage + 32768 + offB[p] + swB;
                uint32_t r0, r1, r2, r3;
                ldsm_x4(aB, r0, r1, r2, r3);
                bh[2*p][0] = r0; bh[2*p][1] = r1; bh[2*p+1][0] = r2; bh[2*p+1][1] = r3;
                ldsm_x4(aB + 16384, r0, r1, r2, r3);
                bl[2*p][0] = r0; bl[2*p][1] = r1; bl[2*p+1][0] = r2; bl[2*p+1][1] = r3;
            }
            #pragma unroll
            for (int mi = 0; mi < 4; mi++)
                #pragma unroll
                for (int ni = 0; ni < 4; ni++) {
                    mma_bf16(acc[mi][ni], ah[mi], bh[ni]);
                    mma_bf16(acc[mi][ni], ah[mi], bl[ni]);
                    mma_bf16(acc[mi][ni], al[mi], bh[ni]);
                }
        }
        __syncthreads();
    }

    // ---- epilogue ----
    const int qr = lane >> 2, qc = (lane & 3) * 2;
    #pragma unroll
    for (int mi = 0; mi < 4; mi++) {
        const int row = m0 + wm * 64 + mi * 16 + qr;
        #pragma unroll
        for (int ni = 0; ni < 4; ni++) {
            const int col = n0 + wn * 32 + ni * 8 + qc;
            float b0 = bias ? bias[col]     : 0.f;
            float b1 = bias ? bias[col + 1] : 0.f;
            float2 v0 = make_float2(acc[mi][ni][0] + b0, acc[mi][ni][1] + b1);
            float2 v1 = make_float2(acc[mi][ni][2] + b0, acc[mi][ni][3] + b1);
            *(float2*)(C + (size_t)row * N + col)       = v0;
            *(float2*)(C + (size_t)(row + 8) * N + col) = v1;
        }
    }
}

// =====================================================================
// rope table (fp64 math once; matches R2's 1.3e-6-class accuracy)
// =====================================================================
__global__ __launch_bounds__(256) void rope_table_kernel()
{
    int idx = blockIdx.x * 256 + threadIdx.x;   // 0 .. LL*64-1
    if (idx >= LL * 64) return;
    int t = idx >> 6, j = idx & 63;
    float invf = (float)exp(-(double)j * 9.210340371976184 / 64.0);
    float ang = (float)t * invf;
    double sd, cd; sincos((double)ang, &sd, &cd);
    g_cos[idx] = (float)cd;
    g_sin[idx] = (float)sd;
}

// =====================================================================
// RoPE + elu+1 + head-major transpose (apply=1), or plain transpose (apply=0)
// =====================================================================
__global__ __launch_bounds__(256) void rope_phi_kernel(
    const float* __restrict__ in, float* __restrict__ out, int apply)
{
    const int m = blockIdx.x;
    const int b = m >> 11;
    const int t = m & (LL - 1);
    if (apply) {
        for (int p = threadIdx.x; p < HH * 64; p += blockDim.x) {
            const int h = p >> 6, j = p & 63;
            float xe = in[(size_t)m * HID + h * DD + j];
            float xo = in[(size_t)m * HID + h * DD + 64 + j];
            float c = g_cos[t * 64 + j];
            float s = g_sin[t * 64 + j];
            float oe = xe * c - xo * s;
            float oo = xe * s + xo * c;
            oe = (oe > 0.f) ? (oe + 1.f) : expf(oe);
            oo = (oo > 0.f) ? (oo + 1.f) : expf(oo);
            size_t base = ((size_t)(b * HH + h) * LL + t) * DD;
            out[base + j]      = oe;
            out[base + 64 + j] = oo;
        }
    } else {
        for (int p = threadIdx.x; p < HID; p += blockDim.x) {
            const int h = p >> 7, d = p & 127;
            out[((size_t)(b * HH + h) * LL + t) * DD + d] = in[(size_t)m * HID + p];
        }
    }
}

// =====================================================================
// beta = clip(sigmoid(x @ Wg + bg), 0.8, 0.9995), stored [b*H+h][t]
// =====================================================================
__global__ __launch_bounds__(512) void beta_kernel(
    const float* __restrict__ x, const float* __restrict__ Wg,
    const float* __restrict__ bg, float* __restrict__ beta)
{
    __shared__ float row[HID];
    const int m = blockIdx.x;
    for (int i = threadIdx.x; i < HID; i += 512) row[i] = x[(size_t)m * HID + i];
    __syncthreads();
    const int w = threadIdx.x >> 5, lane = threadIdx.x & 31;
    float s = 0.f;
    for (int d = lane; d < HID; d += 32) s = fmaf(row[d], Wg[d * HH + w], s);
    #pragma unroll
    for (int o = 16; o; o >>= 1) s += __shfl_xor_sync(0xffffffffu, s, o);
    if (lane == 0) {
        s += bg[w];
        float bt = 1.f / (1.f + expf(-s));
        bt = fminf(fmaxf(bt, 0.8f), 0.9995f);
        const int b = m >> 11, t = m & (LL - 1);
        beta[(size_t)(b * HH + w) * LL + t] = bt;
    }
}

// =====================================================================
// Chunked decayed-linear-attention scan (unchanged from passing R2).
// =====================================================================
__global__ __launch_bounds__(256) void scan_kernel(
    const float* __restrict__ gq, const float* __restrict__ gk,
    const float* __restrict__ gv, const float* __restrict__ gbeta,
    float* __restrict__ gy)
{
    extern __shared__ float sm[];
    float* Qt  = sm;
    float* Kt  = Qt  + 128*68;
    float* Vs  = Kt  + 128*68;
    float* At  = Vs  + 64*36;
    float* Ssm = At  + 64*68;
    float* z   = Ssm + 128*36;
    float* Lc  = z   + 128;
    float* eLc = Lc  + 64;
    float* ksc = eLc + 64;
    float* rsum= ksc + 64;
    float* qz  = rsum+ 64;
    float* bl  = qz  + 64;

    const int tid   = threadIdx.x;
    const int bh    = blockIdx.x / NSPLIT;
    const int split = blockIdx.x % NSPLIT;
    const int b = bh >> 4, h = bh & 15;

    const float* qp = gq + (size_t)bh*LL*DD;
    const float* kp = gk + (size_t)bh*LL*DD;
    const float* vp = gv + (size_t)bh*LL*DD + split*DV;
    const float* bp = gbeta + (size_t)bh*LL;
    float*       yp = gy + (size_t)b*LL*HID + h*DD + split*DV;

    const int txA = tid & 15, tyA = tid >> 4;
    const int txO = tid & 7,  tyO = tid >> 3;

    for (int i = tid; i < 128*36; i += 256) Ssm[i] = 0.f;
    if (tid < 128) z[tid] = 0.f;

    for (int ch = 0; ch < LL/CHK; ch++) {
        const int t0 = ch * CHK;
        __syncthreads();
        for (int idx = tid; idx < CHK*128; idx += 256) {
            const int i = idx >> 7, d = idx & 127;
            Qt[d*68 + i] = qp[(size_t)(t0+i)*DD + d];
            Kt[d*68 + i] = kp[(size_t)(t0+i)*DD + d];
        }
        for (int idx = tid; idx < CHK*DV; idx += 256) {
            const int i = idx >> 5, e = idx & 31;
            Vs[i*36 + e] = vp[(size_t)(t0+i)*DD + e];
        }
        if (tid < CHK) bl[tid] = logf(bp[t0+tid]);
        __syncthreads();
        if (tid == 0) {
            float a = 0.f;
            for (int i = 0; i < CHK; i++) { a += bl[i]; Lc[i] = a; }
        }
        __syncthreads();

        float accA[4][4];
        #pragma unroll
        for (int i=0;i<4;i++) { accA[i][0]=0;accA[i][1]=0;accA[i][2]=0;accA[i][3]=0; }
        for (int k = 0; k < 128; k++) {
            float4 qa = *(float4*)&Qt[k*68 + (tyA<<2)];
            float4 kb = *(float4*)&Kt[k*68 + (txA<<2)];
            const float qv[4] = {qa.x,qa.y,qa.z,qa.w};
            const float kv[4] = {kb.x,kb.y,kb.z,kb.w};
            #pragma unroll
            for (int i=0;i<4;i++)
                #pragma unroll
                for (int s=0;s<4;s++)
                    accA[i][s] = fmaf(qv[i], kv[s], accA[i][s]);
        }
        if (tid < CHK) {
            const int i = tid;
            eLc[i] = expf(Lc[i]);
            ksc[i] = expf(Lc[CHK-1] - Lc[i]);
            float s = 0.f;
            for (int d = 0; d < 128; d++) s = fmaf(Qt[d*68 + i], z[d], s);
            qz[i] = s;
        }
        #pragma unroll
        for (int ii=0; ii<4; ii++) {
            const int i = (tyA<<2) + ii;
            #pragma unroll
            for (int ss=0; ss<4; ss++) {
                const int s = (txA<<2) + ss;
                At[s*68 + i] = (s <= i) ? accA[ii][ss]*expf(Lc[i]-Lc[s]) : 0.f;
            }
        }
        __syncthreads();
        if (tid < CHK) {
            float s = 0.f;
            for (int sI = 0; sI < CHK; sI++) s += At[sI*68 + tid];
            rsum[tid] = s;
        }
        __syncthreads();

        float oA[2][4] = {{0,0,0,0},{0,0,0,0}};
        float oI[2][4] = {{0,0,0,0},{0,0,0,0}};
        for (int s = 0; s < CHK; s++) {
            const float a0 = At[s*68 + (tyO<<1)];
            const float a1 = At[s*68 + (tyO<<1) + 1];
            const float4 v4 = *(float4*)&Vs[s*36 + (txO<<2)];
            oA[0][0]=fmaf(a0,v4.x,oA[0][0]); oA[0][1]=fmaf(a0,v4.y,oA[0][1]);
            oA[0][2]=fmaf(a0,v4.z,oA[0][2]); oA[0][3]=fmaf(a0,v4.w,oA[0][3]);
            oA[1][0]=fmaf(a1,v4.x,oA[1][0]); oA[1][1]=fmaf(a1,v4.y,oA[1][1]);
            oA[1][2]=fmaf(a1,v4.z,oA[1][2]); oA[1][3]=fmaf(a1,v4.w,oA[1][3]);
        }
        for (int d = 0; d < 128; d++) {
            const float q0 = Qt[d*68 + (tyO<<1)];
            const float q1 = Qt[d*68 + (tyO<<1) + 1];
            const float4 s4 = *(float4*)&Ssm[d*36 + (txO<<2)];
            oI[0][0]=fmaf(q0,s4.x,oI[0][0]); oI[0][1]=fmaf(q0,s4.y,oI[0][1]);
            oI[0][2]=fmaf(q0,s4.z,oI[0][2]); oI[0][3]=fmaf(q0,s4.w,oI[0][3]);
            oI[1][0]=fmaf(q1,s4.x,oI[1][0]); oI[1][1]=fmaf(q1,s4.y,oI[1][1]);
            oI[1][2]=fmaf(q1,s4.z,oI[1][2]); oI[1][3]=fmaf(q1,s4.w,oI[1][3]);
        }
        #pragma unroll
        for (int r=0; r<2; r++) {
            const int i = (tyO<<1) + r;
            const float g = eLc[i];
            const float inv = 1.f / (rsum[i] + g*qz[i] + 1e-6f);
            float4 o;
            o.x = (oA[r][0] + g*oI[r][0]) * inv;
            o.y = (oA[r][1] + g*oI[r][1]) * inv;
            o.z = (oA[r][2] + g*oI[r][2]) * inv;
            o.w = (oA[r][3] + g*oI[r][3]) * inv;
            *(float4*)&yp[(size_t)(t0+i)*HID + (txO<<2)] = o;
        }
        __syncthreads();

        const float G = eLc[CHK-1];
        {
            float accS[4][4];
            #pragma unroll
            for (int i=0;i<4;i++){accS[i][0]=0;accS[i][1]=0;accS[i][2]=0;accS[i][3]=0;}
            const int d0 = tyO << 2;
            for (int s = 0; s < CHK; s++) {
                const float sc = ksc[s];
                const float4 v4 = *(float4*)&Vs[s*36 + (txO<<2)];
                float kk[4];
                #pragma unroll
                for (int dd=0; dd<4; dd++) kk[dd] = Kt[(d0+dd)*68 + s] * sc;
                #pragma unroll
                for (int dd=0; dd<4; dd++) {
                    accS[dd][0]=fmaf(kk[dd],v4.x,accS[dd][0]);
                    accS[dd][1]=fmaf(kk[dd],v4.y,accS[dd][1]);
                    accS[dd][2]=fmaf(kk[dd],v4.z,accS[dd][2]);
                    accS[dd][3]=fmaf(kk[dd],v4.w,accS[dd][3]);
                }
            }
            #pragma unroll
            for (int dd=0; dd<4; dd++) {
                float4 sv = *(float4*)&Ssm[(d0+dd)*36 + (txO<<2)];
                sv.x = fmaf(G, sv.x, accS[dd][0]);
                sv.y = fmaf(G, sv.y, accS[dd][1]);
                sv.z = fmaf(G, sv.z, accS[dd][2]);
                sv.w = fmaf(G, sv.w, accS[dd][3]);
                *(float4*)&Ssm[(d0+dd)*36 + (txO<<2)] = sv;
            }
        }
        if (tid < 128) {
            float zv = z[tid] * G;
            for (int s = 0; s < CHK; s++) zv = fmaf(Kt[tid*68 + s], ksc[s], zv);
            z[tid] = zv;
        }
    }
}

// =====================================================================
// launch
// =====================================================================
#define SCAN_SMEM ((128*68*2 + 64*36 + 64*68 + 128*36 + 128 + 6*64) * 4)

extern "C" void kernel_launch(void* const* d_in, const int* in_sizes, int n_in,
                              void* d_out, int out_size)
{
    const float* x  = (const float*)d_in[0];
    const float* Wq = (const float*)d_in[1];
    const float* Wk = (const float*)d_in[2];
    const float* Wv = (const float*)d_in[3];
    const float* Wg = (const float*)d_in[4];
    const float* bg = (const float*)d_in[5];
    const float* Wo = (const float*)d_in[6];
    const float* bo = (const float*)d_in[7];
    float* out = (float*)d_out;

    float *raw, *q, *k, *v, *y, *beta;
    __nv_bfloat16 *ahi, *alo, *whi, *wlo;
    cudaGetSymbolAddress((void**)&raw,  g_raw);
    cudaGetSymbolAddress((void**)&q,    g_q);
    cudaGetSymbolAddress((void**)&k,    g_k);
    cudaGetSymbolAddress((void**)&v,    g_v);
    cudaGetSymbolAddress((void**)&y,    g_y);
    cudaGetSymbolAddress((void**)&beta, g_beta);
    cudaGetSymbolAddress((void**)&ahi,  g_ahi);
    cudaGetSymbolAddress((void**)&alo,  g_alo);
    cudaGetSymbolAddress((void**)&whi,  g_whi);
    cudaGetSymbolAddress((void**)&wlo,  g_wlo);

    cudaFuncSetAttribute(scan_kernel,
        cudaFuncAttributeMaxDynamicSharedMemorySize, SCAN_SMEM);
    cudaFuncSetAttribute(gemm_tc_kernel,
        cudaFuncAttributeMaxDynamicSharedMemorySize, GEMM_SMEM);

    const dim3 wgrid(HID/32, HID/32);        // (64, 64)
    const dim3 wblk(32, 8);
    const dim3 ggrid(HID/128, MM/128);       // (16, 32)
    const size_t WSZ = (size_t)HID*HID;

    // weight transposes + splits
    cvt_w_kernel<<<wgrid, wblk>>>(Wq, whi + 0*WSZ, wlo + 0*WSZ);
    cvt_w_kernel<<<wgrid, wblk>>>(Wk, whi + 1*WSZ, wlo + 1*WSZ);
    cvt_w_kernel<<<wgrid, wblk>>>(Wv, whi + 2*WSZ, wlo + 2*WSZ);
    cvt_w_kernel<<<wgrid, wblk>>>(Wo, whi + 3*WSZ, wlo + 3*WSZ);
    // x split + rope table
    cvt_split_kernel<<<(MM*HID/4 + 255)/256, 256>>>((const float4*)x, ahi, alo, MM*HID/4);
    rope_table_kernel<<<(LL*64 + 255)/256, 256>>>();

    // q/k/v projections on tensor cores (mma.sync)
    gemm_tc_kernel<<<ggrid, 256, GEMM_SMEM>>>(ahi, alo, whi + 0*WSZ, wlo + 0*WSZ,
                                              nullptr, raw, MM, HID, HID);
    rope_phi_kernel<<<MM, 256>>>(raw, q, 1);
    gemm_tc_kernel<<<ggrid, 256, GEMM_SMEM>>>(ahi, alo, whi + 1*WSZ, wlo + 1*WSZ,
                                              nullptr, raw, MM, HID, HID);
    rope_phi_kernel<<<MM, 256>>>(raw, k, 1);
    gemm_tc_kernel<<<ggrid, 256, GEMM_SMEM>>>(ahi, alo, whi + 2*WSZ, wlo + 2*WSZ,
                                              nullptr, raw, MM, HID, HID);
    rope_phi_kernel<<<MM, 256>>>(raw, v, 0);
    beta_kernel<<<MM, 512>>>(x, Wg, bg, beta);

    scan_kernel<<<BB*HH*NSPLIT, 256, SCAN_SMEM>>>(q, k, v, beta, y);

    // output projection (reuse ahi/alo for y)
    cvt_split_kernel<<<(MM*HID/4 + 255)/256, 256>>>((const float4*)y, ahi, alo, MM*HID/4);
    gemm_tc_kernel<<<ggrid, 256, GEMM_SMEM>>>(ahi, alo, whi + 3*WSZ, wlo + 3*WSZ,
                                              bo, out, MM, HID, HID);
}

// round 8
// speedup vs baseline: 2.5444x; 1.0166x over previous
#include <cuda_runtime.h>
#include <cuda_bf16.h>
#include <math.h>
#include <stdint.h>

// Problem constants
#define BB   2
#define LL   2048
#define HID  2048
#define HH   16
#define DD   128
#define MM   (BB*LL)          // 4096
#define CHK  64               // scan chunk length
#define DV   32               // v-dim split per scan block
#define NSPLIT 4              // 128 / DV

// ---------------- device scratch (no cudaMalloc allowed) ----------------
__device__ __align__(256) float g_q   [MM*HID];     // phi_q [b*H+h][t][d]
__device__ __align__(256) float g_k   [MM*HID];     // phi_k
__device__ __align__(256) float g_v   [MM*HID];     // v
__device__ __align__(256) float g_beta[BB*HH*LL];   // [b*H+h][t]

// bf16 split buffers
__device__ __align__(256) __nv_bfloat16 g_ahi[MM*HID];       // x (then y) hi
__device__ __align__(256) __nv_bfloat16 g_alo[MM*HID];       // x (then y) lo
__device__ __align__(256) __nv_bfloat16 g_whi[4*HID*HID];    // W^T hi (q,k,v,o concat)
__device__ __align__(256) __nv_bfloat16 g_wlo[4*HID*HID];    // W^T lo

// rope tables
__device__ float g_cos[LL*64];
__device__ float g_sin[LL*64];

// =====================================================================
// sm_80-era primitives (legal on plain sm_103 ptxas target)
// =====================================================================
__device__ __forceinline__ uint32_t smem_u32(const void* p) {
    uint32_t a;
    asm("{ .reg .u64 t; cvta.to.shared.u64 t, %1; cvt.u32.u64 %0, t; }"
        : "=r"(a) : "l"(p));
    return a;
}
__device__ __forceinline__ void ldsm_x4(uint32_t addr, uint32_t& r0, uint32_t& r1,
                                        uint32_t& r2, uint32_t& r3) {
    asm volatile("ldmatrix.sync.aligned.m8n8.x4.shared.b16 {%0,%1,%2,%3}, [%4];"
        : "=r"(r0), "=r"(r1), "=r"(r2), "=r"(r3) : "r"(addr));
}
__device__ __forceinline__ void mma_bf16(float* c, const uint32_t* a, const uint32_t* b) {
    asm volatile(
        "mma.sync.aligned.m16n8k16.row.col.f32.bf16.bf16.f32 "
        "{%0,%1,%2,%3}, {%4,%5,%6,%7}, {%8,%9}, {%0,%1,%2,%3};"
        : "+f"(c[0]), "+f"(c[1]), "+f"(c[2]), "+f"(c[3])
        : "r"(a[0]), "r"(a[1]), "r"(a[2]), "r"(a[3]), "r"(b[0]), "r"(b[1]));
}
#define CP_ASYNC16(dst, src) \
    asm volatile("cp.async.cg.shared.global [%0], [%1], 16;" :: "r"(dst), "l"(src))
#define CP_COMMIT() asm volatile("cp.async.commit_group;" ::: "memory")
#define CP_WAIT(n)  asm volatile("cp.async.wait_group %0;" :: "n"(n) : "memory")

// =====================================================================
// bf16 split conversion: hi = bf16(x), lo = bf16(x - hi)
// =====================================================================
__global__ __launch_bounds__(256) void cvt_split_kernel(
    const float4* __restrict__ in, __nv_bfloat16* __restrict__ hi,
    __nv_bfloat16* __restrict__ lo, int n4)
{
    int i = blockIdx.x * 256 + threadIdx.x;
    if (i >= n4) return;
    float4 v = in[i];
    float a[4] = {v.x, v.y, v.z, v.w};
    __nv_bfloat16 hb[4], lb[4];
    #pragma unroll
    for (int j = 0; j < 4; j++) {
        hb[j] = __float2bfloat16(a[j]);
        lb[j] = __float2bfloat16(a[j] - __bfloat162float(hb[j]));
    }
    __nv_bfloat162 h0, h1, l0, l1;
    h0.x = hb[0]; h0.y = hb[1]; h1.x = hb[2]; h1.y = hb[3];
    l0.x = lb[0]; l0.y = lb[1]; l1.x = lb[2]; l1.y = lb[3];
    *(__nv_bfloat162*)(hi + 4*(size_t)i)     = h0;
    *(__nv_bfloat162*)(hi + 4*(size_t)i + 2) = h1;
    *(__nv_bfloat162*)(lo + 4*(size_t)i)     = l0;
    *(__nv_bfloat162*)(lo + 4*(size_t)i + 2) = l1;
}

// W [K=HID][N=HID] fp32 -> W^T hi/lo bf16 [N][K]
__global__ __launch_bounds__(256) void cvt_w_kernel(
    const float* __restrict__ W, __nv_bfloat16* __restrict__ th,
    __nv_bfloat16* __restrict__ tl)
{
    __shared__ float t[32][33];
    const int k0 = blockIdx.y * 32, n0 = blockIdx.x * 32;
    const int tx = threadIdx.x, ty = threadIdx.y;   // block (32,8)
    for (int i = ty; i < 32; i += 8)
        t[i][tx] = W[(size_t)(k0 + i) * HID + n0 + tx];
    __syncthreads();
    for (int i = ty; i < 32; i += 8) {
        float x = t[tx][i];                    // W[k0+tx][n0+i]
        __nv_bfloat16 h = __float2bfloat16(x);
        __nv_bfloat16 l = __float2bfloat16(x - __bfloat162float(h));
        size_t o = (size_t)(n0 + i) * HID + k0 + tx;
        th[o] = h; tl[o] = l;
    }
}

// =====================================================================
// mma.sync GEMM with fused epilogue.
// C[M,N] = A[M,K] @ W[K,N] (+bias) using bf16 hi/lo split (3 passes).
// A as Ah/Al [M][K]; W transposed as Bh/Bl [Nb][K] (col-major B),
// Nb = gridDim.x*128 rows starting at Bh/Bl pointer.
// fuse=1 (QKV launch, grid.x=48): n-tile 0-15 -> Q (rope+phi), 16-31 -> K
//   (rope+phi), 32-47 -> V (transpose), all written head-major to outQ/K/V.
// fuse=0: plain write of C with bias.
// 128x128 CTA tile, 8 warps (2x4), 64x32 warp tile, K-stage 64,
// 3-stage cp.async pipeline, xor-swizzled smem for ldmatrix.
// =====================================================================
#define GEMM_SMEM (3 * 4 * 16384)   // 3 stages x (Ah,Al,Bh,Bl) x 16KB = 192KB

__global__ __launch_bounds__(256, 1) void gemm_tc_kernel(
    const __nv_bfloat16* __restrict__ Ah, const __nv_bfloat16* __restrict__ Al,
    const __nv_bfloat16* __restrict__ Bh, const __nv_bfloat16* __restrict__ Bl,
    const float* __restrict__ bias, float* __restrict__ C,
    float* __restrict__ outQ, float* __restrict__ outK, float* __restrict__ outV,
    int fuse, int M, int N, int K)
{
    extern __shared__ __align__(1024) char smem[];
    const uint32_t sbase = smem_u32(smem);

    const int tid  = threadIdx.x;
    const int wid  = tid >> 5, lane = tid & 31;
    const int wm   = wid >> 2, wn = wid & 3;       // warp grid 2x4
    const int m0   = blockIdx.y * 128;
    const int bn0  = blockIdx.x * 128;             // row into B (concat N)

    const __nv_bfloat16* gsrc[4] = {Ah, Al, Bh, Bl};
    const int NS = K >> 6;                          // K/64 stages

    // ---- cp.async one K-stage into buffer buf (0/1/2) ----
    auto load_stage = [&](int buf, int k0e) {
        const uint32_t bs = sbase + buf * 65536;
        #pragma unroll
        for (int p = 0; p < 16; p++) {
            int idx = tid + p * 256;               // 0..4095
            int j   = idx >> 10;                   // tile 0..3
            int i   = idx & 1023;
            int r   = i >> 3, ch = i & 7;
            int phys = ch ^ (r & 7);
            uint32_t dst = bs + j * 16384 + r * 128 + phys * 16;
            int grow = (j < 2 ? m0 : bn0) + r;
            const __nv_bfloat16* src = gsrc[j] + (size_t)grow * K + k0e + ch * 8;
            CP_ASYNC16(dst, src);
        }
        CP_COMMIT();
    };

    // per-lane ldmatrix address components
    const int lw  = lane & 7;
    const int gA  = (lane >> 4) & 1;               // A: k-half select
    const int gB  = (lane >> 3) & 1;               // B: k-half select
    uint32_t offA[4], offB[2];
    #pragma unroll
    for (int mi = 0; mi < 4; mi++)
        offA[mi] = (uint32_t)(wm * 64 + mi * 16 + (lane & 15)) * 128;
    #pragma unroll
    for (int p = 0; p < 2; p++)
        offB[p] = (uint32_t)(wn * 32 + p * 16 + ((lane >> 4) & 1) * 8 + lw) * 128;

    float acc[4][4][4];
    #pragma unroll
    for (int mi = 0; mi < 4; mi++)
        #pragma unroll
        for (int ni = 0; ni < 4; ni++) {
            acc[mi][ni][0] = 0.f; acc[mi][ni][1] = 0.f;
            acc[mi][ni][2] = 0.f; acc[mi][ni][3] = 0.f;
        }

    load_stage(0, 0);
    load_stage(1, 64);

    for (int s = 0; s < NS; s++) {
        if (s + 1 < NS) { CP_WAIT(1); } else { CP_WAIT(0); }
        __syncthreads();
        if (s + 2 < NS) load_stage((s + 2) % 3, (s + 2) * 64);

        const uint32_t stage = sbase + (s % 3) * 65536;
        #pragma unroll
        for (int kk = 0; kk < 4; kk++) {
            const uint32_t swA = (uint32_t)(((kk * 2 + gA) ^ lw) << 4);
            const uint32_t swB = (uint32_t)(((kk * 2 + gB) ^ lw) << 4);
            uint32_t ah[4][4], al[4][4];
            #pragma unroll
            for (int mi = 0; mi < 4; mi++) {
                uint32_t aA = stage + offA[mi] + swA;
                ldsm_x4(aA,          ah[mi][0], ah[mi][1], ah[mi][2], ah[mi][3]);
                ldsm_x4(aA + 16384,  al[mi][0], al[mi][1], al[mi][2], al[mi][3]);
            }
            uint32_t bh[4][2], bl[4][2];
            #pragma unroll
            for (int p = 0; p < 2; p++) {
                uint32_t aB = stage + 32768 + offB[p] + swB;
                uint32_t r0, r1, r2, r3;
                ldsm_x4(aB, r0, r1, r2, r3);
                bh[2*p][0] = r0; bh[2*p][1] = r1; bh[2*p+1][0] = r2; bh[2*p+1][1] = r3;
                ldsm_x4(aB + 16384, r0, r1, r2, r3);
                bl[2*p][0] = r0; bl[2*p][1] = r1; bl[2*p+1][0] = r2; bl[2*p+1][1] = r3;
            }
            #pragma unroll
            for (int mi = 0; mi < 4; mi++)
                #pragma unroll
                for (int ni = 0; ni < 4; ni++) {
                    mma_bf16(acc[mi][ni], ah[mi], bh[ni]);
                    mma_bf16(acc[mi][ni], ah[mi], bl[ni]);
                    mma_bf16(acc[mi][ni], al[mi], bh[ni]);
                }
        }
        __syncthreads();
    }

    const int qr = lane >> 2, qc = (lane & 3) * 2;

    if (!fuse) {
        // ---- plain epilogue: C += bias ----
        #pragma unroll
        for (int mi = 0; mi < 4; mi++) {
            const int row = m0 + wm * 64 + mi * 16 + qr;
            #pragma unroll
            for (int ni = 0; ni < 4; ni++) {
                const int col = bn0 + wn * 32 + ni * 8 + qc;
                float b0 = bias ? bias[col]     : 0.f;
                float b1 = bias ? bias[col + 1] : 0.f;
                float2 v0 = make_float2(acc[mi][ni][0] + b0, acc[mi][ni][1] + b1);
                float2 v1 = make_float2(acc[mi][ni][2] + b0, acc[mi][ni][3] + b1);
                *(float2*)(C + (size_t)row * N + col)       = v0;
                *(float2*)(C + (size_t)(row + 8) * N + col) = v1;
            }
        }
        return;
    }

    // ---- fused QKV epilogue: stage acc tile to smem, then rope/transpose ----
    float* st = (float*)smem;                      // [128][132]
    #pragma unroll
    for (int mi = 0; mi < 4; mi++) {
        const int r0r = wm * 64 + mi * 16 + qr;
        #pragma unroll
        for (int ni = 0; ni < 4; ni++) {
            const int c = wn * 32 + ni * 8 + qc;
            *(float2*)&st[(size_t)r0r * 132 + c] =
                make_float2(acc[mi][ni][0], acc[mi][ni][1]);
            *(float2*)&st[(size_t)(r0r + 8) * 132 + c] =
                make_float2(acc[mi][ni][2], acc[mi][ni][3]);
        }
    }
    __syncthreads();

    const int hIdx = blockIdx.x & 15;              // head
    if (blockIdx.x < 32) {
        // rope + elu+1, head-major
        float* dstBase = (blockIdx.x < 16) ? outQ : outK;
        const int j = tid & 63;
        #pragma unroll 4
        for (int it = 0; it < 32; it++) {
            const int r = (tid >> 6) + it * 4;
            const int tg = m0 + r;
            const int bI = tg >> 11, t = tg & (LL - 1);
            float xe = st[(size_t)r * 132 + j];
            float xo = st[(size_t)r * 132 + 64 + j];
            float c = g_cos[t * 64 + j];
            float s = g_sin[t * 64 + j];
            float oe = xe * c - xo * s;
            float oo = xe * s + xo * c;
            oe = (oe > 0.f) ? (oe + 1.f) : expf(oe);
            oo = (oo > 0.f) ? (oo + 1.f) : expf(oo);
            float* dst = dstBase + ((size_t)(bI * HH + hIdx) * LL + t) * DD;
            dst[j]      = oe;
            dst[j + 64] = oo;
        }
    } else {
        // plain transpose to head-major (V)
        const int d = tid & 127;
        #pragma unroll 4
        for (int it = 0; it < 64; it++) {
            const int r = (tid >> 7) + it * 2;
            const int tg = m0 + r;
            const int bI = tg >> 11, t = tg & (LL - 1);
            outV[((size_t)(bI * HH + hIdx) * LL + t) * DD + d] =
                st[(size_t)r * 132 + d];
        }
    }
}

// =====================================================================
// rope table (fp64 math once; matches R2's 1.3e-6-class accuracy)
// =====================================================================
__global__ __launch_bounds__(256) void rope_table_kernel()
{
    int idx = blockIdx.x * 256 + threadIdx.x;   // 0 .. LL*64-1
    if (idx >= LL * 64) return;
    int t = idx >> 6, j = idx & 63;
    float invf = (float)exp(-(double)j * 9.210340371976184 / 64.0);
    float ang = (float)t * invf;
    double sd, cd; sincos((double)ang, &sd, &cd);
    g_cos[idx] = (float)cd;
    g_sin[idx] = (float)sd;
}

// =====================================================================
// beta = clip(sigmoid(x @ Wg + bg), 0.8, 0.9995), stored [b*H+h][t]
// =====================================================================
__global__ __launch_bounds__(512) void beta_kernel(
    const float* __restrict__ x, const float* __restrict__ Wg,
    const float* __restrict__ bg, float* __restrict__ beta)
{
    __shared__ float row[HID];
    const int m = blockIdx.x;
    for (int i = threadIdx.x; i < HID; i += 512) row[i] = x[(size_t)m * HID + i];
    __syncthreads();
    const int w = threadIdx.x >> 5, lane = threadIdx.x & 31;
    float s = 0.f;
    for (int d = lane; d < HID; d += 32) s = fmaf(row[d], Wg[d * HH + w], s);
    #pragma unroll
    for (int o = 16; o; o >>= 1) s += __shfl_xor_sync(0xffffffffu, s, o);
    if (lane == 0) {
        s += bg[w];
        float bt = 1.f / (1.f + expf(-s));
        bt = fminf(fmaxf(bt, 0.8f), 0.9995f);
        const int b = m >> 11, t = m & (LL - 1);
        beta[(size_t)(b * HH + w) * LL + t] = bt;
    }
}

// =====================================================================
// Chunked decayed-linear-attention scan (R2-verified math).
// Now writes y directly as bf16 hi/lo split (input to the Wo GEMM).
// =====================================================================
__global__ __launch_bounds__(256) void scan_kernel(
    const float* __restrict__ gq, const float* __restrict__ gk,
    const float* __restrict__ gv, const float* __restrict__ gbeta,
    __nv_bfloat16* __restrict__ yhi, __nv_bfloat16* __restrict__ ylo)
{
    extern __shared__ float sm[];
    float* Qt  = sm;
    float* Kt  = Qt  + 128*68;
    float* Vs  = Kt  + 128*68;
    float* At  = Vs  + 64*36;
    float* Ssm = At  + 64*68;
    float* z   = Ssm + 128*36;
    float* Lc  = z   + 128;
    float* eLc = Lc  + 64;
    float* ksc = eLc + 64;
    float* rsum= ksc + 64;
    float* qz  = rsum+ 64;
    float* bl  = qz  + 64;

    const int tid   = threadIdx.x;
    const int bh    = blockIdx.x / NSPLIT;
    const int split = blockIdx.x % NSPLIT;
    const int b = bh >> 4, hd = bh & 15;

    const float* qp = gq + (size_t)bh*LL*DD;
    const float* kp = gk + (size_t)bh*LL*DD;
    const float* vp = gv + (size_t)bh*LL*DD + split*DV;
    const float* bp = gbeta + (size_t)bh*LL;
    const size_t ybase = (size_t)b*LL*HID + hd*DD + split*DV;

    const int txA = tid & 15, tyA = tid >> 4;
    const int txO = tid & 7,  tyO = tid >> 3;

    for (int i = tid; i < 128*36; i += 256) Ssm[i] = 0.f;
    if (tid < 128) z[tid] = 0.f;

    for (int ch = 0; ch < LL/CHK; ch++) {
        const int t0 = ch * CHK;
        __syncthreads();
        for (int idx = tid; idx < CHK*128; idx += 256) {
            const int i = idx >> 7, d = idx & 127;
            Qt[d*68 + i] = qp[(size_t)(t0+i)*DD + d];
            Kt[d*68 + i] = kp[(size_t)(t0+i)*DD + d];
        }
        for (int idx = tid; idx < CHK*DV; idx += 256) {
            const int i = idx >> 5, e = idx & 31;
            Vs[i*36 + e] = vp[(size_t)(t0+i)*DD + e];
        }
        if (tid < CHK) bl[tid] = logf(bp[t0+tid]);
        __syncthreads();
        if (tid == 0) {
            float a = 0.f;
            for (int i = 0; i < CHK; i++) { a += bl[i]; Lc[i] = a; }
        }
        __syncthreads();

        float accA[4][4];
        #pragma unroll
        for (int i=0;i<4;i++) { accA[i][0]=0;accA[i][1]=0;accA[i][2]=0;accA[i][3]=0; }
        for (int k = 0; k < 128; k++) {
            float4 qa = *(float4*)&Qt[k*68 + (tyA<<2)];
            float4 kb = *(float4*)&Kt[k*68 + (txA<<2)];
            const float qv[4] = {qa.x,qa.y,qa.z,qa.w};
            const float kv[4] = {kb.x,kb.y,kb.z,kb.w};
            #pragma unroll
            for (int i=0;i<4;i++)
                #pragma unroll
                for (int s=0;s<4;s++)
                    accA[i][s] = fmaf(qv[i], kv[s], accA[i][s]);
        }
        if (tid < CHK) {
            const int i = tid;
            eLc[i] = expf(Lc[i]);
            ksc[i] = expf(Lc[CHK-1] - Lc[i]);
            float s = 0.f;
            for (int d = 0; d < 128; d++) s = fmaf(Qt[d*68 + i], z[d], s);
            qz[i] = s;
        }
        #pragma unroll
        for (int ii=0; ii<4; ii++) {
            const int i = (tyA<<2) + ii;
            #pragma unroll
            for (int ss=0; ss<4; ss++) {
                const int s = (txA<<2) + ss;
                At[s*68 + i] = (s <= i) ? accA[ii][ss]*expf(Lc[i]-Lc[s]) : 0.f;
            }
        }
        __syncthreads();
        if (tid < CHK) {
            float s = 0.f;
            for (int sI = 0; sI < CHK; sI++) s += At[sI*68 + tid];
            rsum[tid] = s;
        }
        __syncthreads();

        float oA[2][4] = {{0,0,0,0},{0,0,0,0}};
        float oI[2][4] = {{0,0,0,0},{0,0,0,0}};
        for (int s = 0; s < CHK; s++) {
            const float a0 = At[s*68 + (tyO<<1)];
            const float a1 = At[s*68 + (tyO<<1) + 1];
            const float4 v4 = *(float4*)&Vs[s*36 + (txO<<2)];
            oA[0][0]=fmaf(a0,v4.x,oA[0][0]); oA[0][1]=fmaf(a0,v4.y,oA[0][1]);
            oA[0][2]=fmaf(a0,v4.z,oA[0][2]); oA[0][3]=fmaf(a0,v4.w,oA[0][3]);
            oA[1][0]=fmaf(a1,v4.x,oA[1][0]); oA[1][1]=fmaf(a1,v4.y,oA[1][1]);
            oA[1][2]=fmaf(a1,v4.z,oA[1][2]); oA[1][3]=fmaf(a1,v4.w,oA[1][3]);
        }
        for (int d = 0; d < 128; d++) {
            const float q0 = Qt[d*68 + (tyO<<1)];
            const float q1 = Qt[d*68 + (tyO<<1) + 1];
            const float4 s4 = *(float4*)&Ssm[d*36 + (txO<<2)];
            oI[0][0]=fmaf(q0,s4.x,oI[0][0]); oI[0][1]=fmaf(q0,s4.y,oI[0][1]);
            oI[0][2]=fmaf(q0,s4.z,oI[0][2]); oI[0][3]=fmaf(q0,s4.w,oI[0][3]);
            oI[1][0]=fmaf(q1,s4.x,oI[1][0]); oI[1][1]=fmaf(q1,s4.y,oI[1][1]);
            oI[1][2]=fmaf(q1,s4.z,oI[1][2]); oI[1][3]=fmaf(q1,s4.w,oI[1][3]);
        }
        #pragma unroll
        for (int r=0; r<2; r++) {
            const int i = (tyO<<1) + r;
            const float g = eLc[i];
            const float inv = 1.f / (rsum[i] + g*qz[i] + 1e-6f);
            float o[4];
            o[0] = (oA[r][0] + g*oI[r][0]) * inv;
            o[1] = (oA[r][1] + g*oI[r][1]) * inv;
            o[2] = (oA[r][2] + g*oI[r][2]) * inv;
            o[3] = (oA[r][3] + g*oI[r][3]) * inv;
            // hi/lo bf16 split store
            __nv_bfloat16 hb[4], lb[4];
            #pragma unroll
            for (int u = 0; u < 4; u++) {
                hb[u] = __float2bfloat16(o[u]);
                lb[u] = __float2bfloat16(o[u] - __bfloat162float(hb[u]));
            }
            const size_t off = ybase + (size_t)(t0 + i) * HID + (txO << 2);
            __nv_bfloat162 ph0; ph0.x = hb[0]; ph0.y = hb[1];
            __nv_bfloat162 ph1; ph1.x = hb[2]; ph1.y = hb[3];
            __nv_bfloat162 pl0; pl0.x = lb[0]; pl0.y = lb[1];
            __nv_bfloat162 pl1; pl1.x = lb[2]; pl1.y = lb[3];
            *(__nv_bfloat162*)(yhi + off)     = ph0;
            *(__nv_bfloat162*)(yhi + off + 2) = ph1;
            *(__nv_bfloat162*)(ylo + off)     = pl0;
            *(__nv_bfloat162*)(ylo + off + 2) = pl1;
        }
        __syncthreads();

        const float G = eLc[CHK-1];
        {
            float accS[4][4];
            #pragma unroll
            for (int i=0;i<4;i++){accS[i][0]=0;accS[i][1]=0;accS[i][2]=0;accS[i][3]=0;}
            const int d0 = tyO << 2;
            for (int s = 0; s < CHK; s++) {
                const float sc = ksc[s];
                const float4 v4 = *(float4*)&Vs[s*36 + (txO<<2)];
                float kk[4];
                #pragma unroll
                for (int dd=0; dd<4; dd++) kk[dd] = Kt[(d0+dd)*68 + s] * sc;
                #pragma unroll
                for (int dd=0; dd<4; dd++) {
                    accS[dd][0]=fmaf(kk[dd],v4.x,accS[dd][0]);
                    accS[dd][1]=fmaf(kk[dd],v4.y,accS[dd][1]);
                    accS[dd][2]=fmaf(kk[dd],v4.z,accS[dd][2]);
                    accS[dd][3]=fmaf(kk[dd],v4.w,accS[dd][3]);
                }
            }
            #pragma unroll
            for (int dd=0; dd<4; dd++) {
                float4 sv = *(float4*)&Ssm[(d0+dd)*36 + (txO<<2)];
                sv.x = fmaf(G, sv.x, accS[dd][0]);
                sv.y = fmaf(G, sv.y, accS[dd][1]);
                sv.z = fmaf(G, sv.z, accS[dd][2]);
                sv.w = fmaf(G, sv.w, accS[dd][3]);
                *(float4*)&Ssm[(d0+dd)*36 + (txO<<2)] = sv;
            }
        }
        if (tid < 128) {
            float zv = z[tid] * G;
            for (int s = 0; s < CHK; s++) zv = fmaf(Kt[tid*68 + s], ksc[s], zv);
            z[tid] = zv;
        }
    }
}

// =====================================================================
// launch
// =====================================================================
#define SCAN_SMEM ((128*68*2 + 64*36 + 64*68 + 128*36 + 128 + 6*64) * 4)

extern "C" void kernel_launch(void* const* d_in, const int* in_sizes, int n_in,
                              void* d_out, int out_size)
{
    const float* x  = (const float*)d_in[0];
    const float* Wq = (const float*)d_in[1];
    const float* Wk = (const float*)d_in[2];
    const float* Wv = (const float*)d_in[3];
    const float* Wg = (const float*)d_in[4];
    const float* bg = (const float*)d_in[5];
    const float* Wo = (const float*)d_in[6];
    const float* bo = (const float*)d_in[7];
    float* out = (float*)d_out;

    float *q, *k, *v, *beta;
    __nv_bfloat16 *ahi, *alo, *whi, *wlo;
    cudaGetSymbolAddress((void**)&q,    g_q);
    cudaGetSymbolAddress((void**)&k,    g_k);
    cudaGetSymbolAddress((void**)&v,    g_v);
    cudaGetSymbolAddress((void**)&beta, g_beta);
    cudaGetSymbolAddress((void**)&ahi,  g_ahi);
    cudaGetSymbolAddress((void**)&alo,  g_alo);
    cudaGetSymbolAddress((void**)&whi,  g_whi);
    cudaGetSymbolAddress((void**)&wlo,  g_wlo);

    cudaFuncSetAttribute(scan_kernel,
        cudaFuncAttributeMaxDynamicSharedMemorySize, SCAN_SMEM);
    cudaFuncSetAttribute(gemm_tc_kernel,
        cudaFuncAttributeMaxDynamicSharedMemorySize, GEMM_SMEM);

    const dim3 wgrid(HID/32, HID/32);        // (64, 64)
    const dim3 wblk(32, 8);
    const size_t WSZ = (size_t)HID*HID;

    // launch order keeps the fused QKV GEMM at ncu's -s 5 profiling slot
    rope_table_kernel<<<(LL*64 + 255)/256, 256>>>();                       // 0
    cvt_split_kernel<<<(MM*HID/4 + 255)/256, 256>>>(                       // 1
        (const float4*)x, ahi, alo, MM*HID/4);
    cvt_w_kernel<<<wgrid, wblk>>>(Wq, whi + 0*WSZ, wlo + 0*WSZ);           // 2
    cvt_w_kernel<<<wgrid, wblk>>>(Wk, whi + 1*WSZ, wlo + 1*WSZ);           // 3
    cvt_w_kernel<<<wgrid, wblk>>>(Wv, whi + 2*WSZ, wlo + 2*WSZ);           // 4

    // fused QKV projection + rope/phi/transpose epilogue                  // 5
    gemm_tc_kernel<<<dim3(48, MM/128), 256, GEMM_SMEM>>>(
        ahi, alo, whi, wlo, nullptr, nullptr, q, k, v, 1, MM, 3*HID, HID);

    cvt_w_kernel<<<wgrid, wblk>>>(Wo, whi + 3*WSZ, wlo + 3*WSZ);           // 6
    beta_kernel<<<MM, 512>>>(x, Wg, bg, beta);                             // 7

    scan_kernel<<<BB*HH*NSPLIT, 256, SCAN_SMEM>>>(q, k, v, beta, ahi, alo);// 8

    // output projection                                                    // 9
    gemm_tc_kernel<<<dim3(HID/128, MM/128), 256, GEMM_SMEM>>>(
        ahi, alo, whi + 3*WSZ, wlo + 3*WSZ, bo, out,
        nullptr, nullptr, nullptr, 0, MM, HID, HID);
}

// round 10
// speedup vs baseline: 2.6193x; 1.0294x over previous
#include <cuda_runtime.h>
#include <cuda_bf16.h>
#include <math.h>
#include <stdint.h>

// Problem constants
#define BB   2
#define LL   2048
#define HID  2048
#define HH   16
#define DD   128
#define MM   (BB*LL)          // 4096
#define CHK  64               // scan chunk length
#define NCH  (LL/CHK)         // 32 chunks
#define DV   32               // v-dim split per state block
#define NSPLIT 4              // 128 / DV
#define NBH  (BB*HH)          // 32

// ---------------- device scratch (no cudaMalloc allowed) ----------------
__device__ __align__(256) float g_q   [MM*HID];     // phi_q [b*H+h][t][d]
__device__ __align__(256) float g_k   [MM*HID];     // phi_k
__device__ __align__(256) float g_v   [MM*HID];     // v
__device__ __align__(256) float g_beta[NBH*LL];     // [b*H+h][t]

// chunk-factored scan scratch
__device__ __align__(256) float g_At  [NBH*NCH*CHK*CHK];  // decayed+masked A, [bhch][s][i]
__device__ __align__(256) float g_rsum[NBH*NCH*CHK];
__device__ __align__(256) float g_eLc [NBH*NCH*CHK];
__device__ __align__(256) float g_ksc [NBH*NCH*CHK];
__device__ __align__(256) float g_Sst [NBH*NCH*DD*DD];    // S_prev per chunk
__device__ __align__(256) float g_zst [NBH*NCH*DD];       // z_prev per chunk

// bf16 split buffers
__device__ __align__(256) __nv_bfloat16 g_ahi[MM*HID];       // x (then y) hi
__device__ __align__(256) __nv_bfloat16 g_alo[MM*HID];       // x (then y) lo
__device__ __align__(256) __nv_bfloat16 g_whi[4*HID*HID];    // W^T hi (q,k,v,o concat)
__device__ __align__(256) __nv_bfloat16 g_wlo[4*HID*HID];    // W^T lo

// rope tables
__device__ float g_cos[LL*64];
__device__ float g_sin[LL*64];

// =====================================================================
// sm_80-era primitives (legal on plain sm_103 ptxas target)
// =====================================================================
__device__ __forceinline__ uint32_t smem_u32(const void* p) {
    uint32_t a;
    asm("{ .reg .u64 t; cvta.to.shared.u64 t, %1; cvt.u32.u64 %0, t; }"
        : "=r"(a) : "l"(p));
    return a;
}
__device__ __forceinline__ void ldsm_x4(uint32_t addr, uint32_t& r0, uint32_t& r1,
                                        uint32_t& r2, uint32_t& r3) {
    asm volatile("ldmatrix.sync.aligned.m8n8.x4.shared.b16 {%0,%1,%2,%3}, [%4];"
        : "=r"(r0), "=r"(r1), "=r"(r2), "=r"(r3) : "r"(addr));
}
__device__ __forceinline__ void mma_bf16(float* c, const uint32_t* a, const uint32_t* b) {
    asm volatile(
        "mma.sync.aligned.m16n8k16.row.col.f32.bf16.bf16.f32 "
        "{%0,%1,%2,%3}, {%4,%5,%6,%7}, {%8,%9}, {%0,%1,%2,%3};"
        : "+f"(c[0]), "+f"(c[1]), "+f"(c[2]), "+f"(c[3])
        : "r"(a[0]), "r"(a[1]), "r"(a[2]), "r"(a[3]), "r"(b[0]), "r"(b[1]));
}
#define CP_ASYNC16(dst, src) \
    asm volatile("cp.async.cg.shared.global [%0], [%1], 16;" :: "r"(dst), "l"(src))
#define CP_COMMIT() asm volatile("cp.async.commit_group;" ::: "memory")
#define CP_WAIT(n)  asm volatile("cp.async.wait_group %0;" :: "n"(n) : "memory")

// =====================================================================
// bf16 split conversion: hi = bf16(x), lo = bf16(x - hi)
// =====================================================================
__global__ __launch_bounds__(256) void cvt_split_kernel(
    const float4* __restrict__ in, __nv_bfloat16* __restrict__ hi,
    __nv_bfloat16* __restrict__ lo, int n4)
{
    int i = blockIdx.x * 256 + threadIdx.x;
    if (i >= n4) return;
    float4 v = in[i];
    float a[4] = {v.x, v.y, v.z, v.w};
    __nv_bfloat16 hb[4], lb[4];
    #pragma unroll
    for (int j = 0; j < 4; j++) {
        hb[j] = __float2bfloat16(a[j]);
        lb[j] = __float2bfloat16(a[j] - __bfloat162float(hb[j]));
    }
    __nv_bfloat162 h0, h1, l0, l1;
    h0.x = hb[0]; h0.y = hb[1]; h1.x = hb[2]; h1.y = hb[3];
    l0.x = lb[0]; l0.y = lb[1]; l1.x = lb[2]; l1.y = lb[3];
    *(__nv_bfloat162*)(hi + 4*(size_t)i)     = h0;
    *(__nv_bfloat162*)(hi + 4*(size_t)i + 2) = h1;
    *(__nv_bfloat162*)(lo + 4*(size_t)i)     = l0;
    *(__nv_bfloat162*)(lo + 4*(size_t)i + 2) = l1;
}

// W [K=HID][N=HID] fp32 -> W^T hi/lo bf16 [N][K]
__global__ __launch_bounds__(256) void cvt_w_kernel(
    const float* __restrict__ W, __nv_bfloat16* __restrict__ th,
    __nv_bfloat16* __restrict__ tl)
{
    __shared__ float t[32][33];
    const int k0 = blockIdx.y * 32, n0 = blockIdx.x * 32;
    const int tx = threadIdx.x, ty = threadIdx.y;   // block (32,8)
    for (int i = ty; i < 32; i += 8)
        t[i][tx] = W[(size_t)(k0 + i) * HID + n0 + tx];
    __syncthreads();
    for (int i = ty; i < 32; i += 8) {
        float x = t[tx][i];                    // W[k0+tx][n0+i]
        __nv_bfloat16 h = __float2bfloat16(x);
        __nv_bfloat16 l = __float2bfloat16(x - __bfloat162float(h));
        size_t o = (size_t)(n0 + i) * HID + k0 + tx;
        th[o] = h; tl[o] = l;
    }
}

// =====================================================================
// mma.sync GEMM with fused epilogue (unchanged from R8 pass).
// =====================================================================
#define GEMM_SMEM (3 * 4 * 16384)   // 3 stages x (Ah,Al,Bh,Bl) x 16KB = 192KB

__global__ __launch_bounds__(256, 1) void gemm_tc_kernel(
    const __nv_bfloat16* __restrict__ Ah, const __nv_bfloat16* __restrict__ Al,
    const __nv_bfloat16* __restrict__ Bh, const __nv_bfloat16* __restrict__ Bl,
    const float* __restrict__ bias, float* __restrict__ C,
    float* __restrict__ outQ, float* __restrict__ outK, float* __restrict__ outV,
    int fuse, int M, int N, int K)
{
    extern __shared__ __align__(1024) char smem[];
    const uint32_t sbase = smem_u32(smem);

    const int tid  = threadIdx.x;
    const int wid  = tid >> 5, lane = tid & 31;
    const int wm   = wid >> 2, wn = wid & 3;       // warp grid 2x4
    const int m0   = blockIdx.y * 128;
    const int bn0  = blockIdx.x * 128;             // row into B (concat N)

    const __nv_bfloat16* gsrc[4] = {Ah, Al, Bh, Bl};
    const int NS = K >> 6;                          // K/64 stages

    auto load_stage = [&](int buf, int k0e) {
        const uint32_t bs = sbase + buf * 65536;
        #pragma unroll
        for (int p = 0; p < 16; p++) {
            int idx = tid + p * 256;
            int j   = idx >> 10;
            int i   = idx & 1023;
            int r   = i >> 3, ch = i & 7;
            int phys = ch ^ (r & 7);
            uint32_t dst = bs + j * 16384 + r * 128 + phys * 16;
            int grow = (j < 2 ? m0 : bn0) + r;
            const __nv_bfloat16* src = gsrc[j] + (size_t)grow * K + k0e + ch * 8;
            CP_ASYNC16(dst, src);
        }
        CP_COMMIT();
    };

    const int lw  = lane & 7;
    const int gA  = (lane >> 4) & 1;
    const int gB  = (lane >> 3) & 1;
    uint32_t offA[4], offB[2];
    #pragma unroll
    for (int mi = 0; mi < 4; mi++)
        offA[mi] = (uint32_t)(wm * 64 + mi * 16 + (lane & 15)) * 128;
    #pragma unroll
    for (int p = 0; p < 2; p++)
        offB[p] = (uint32_t)(wn * 32 + p * 16 + ((lane >> 4) & 1) * 8 + lw) * 128;

    float acc[4][4][4];
    #pragma unroll
    for (int mi = 0; mi < 4; mi++)
        #pragma unroll
        for (int ni = 0; ni < 4; ni++) {
            acc[mi][ni][0] = 0.f; acc[mi][ni][1] = 0.f;
            acc[mi][ni][2] = 0.f; acc[mi][ni][3] = 0.f;
        }

    load_stage(0, 0);
    load_stage(1, 64);

    for (int s = 0; s < NS; s++) {
        if (s + 1 < NS) { CP_WAIT(1); } else { CP_WAIT(0); }
        __syncthreads();
        if (s + 2 < NS) load_stage((s + 2) % 3, (s + 2) * 64);

        const uint32_t stage = sbase + (s % 3) * 65536;
        #pragma unroll
        for (int kk = 0; kk < 4; kk++) {
            const uint32_t swA = (uint32_t)(((kk * 2 + gA) ^ lw) << 4);
            const uint32_t swB = (uint32_t)(((kk * 2 + gB) ^ lw) << 4);
            uint32_t ah[4][4], al[4][4];
            #pragma unroll
            for (int mi = 0; mi < 4; mi++) {
                uint32_t aA = stage + offA[mi] + swA;
                ldsm_x4(aA,          ah[mi][0], ah[mi][1], ah[mi][2], ah[mi][3]);
                ldsm_x4(aA + 16384,  al[mi][0], al[mi][1], al[mi][2], al[mi][3]);
            }
            uint32_t bh[4][2], bl[4][2];
            #pragma unroll
            for (int p = 0; p < 2; p++) {
                uint32_t aB = stage + 32768 + offB[p] + swB;
                uint32_t r0, r1, r2, r3;
                ldsm_x4(aB, r0, r1, r2, r3);
                bh[2*p][0] = r0; bh[2*p][1] = r1; bh[2*p+1][0] = r2; bh[2*p+1][1] = r3;
                ldsm_x4(aB + 16384, r0, r1, r2, r3);
                bl[2*p][0] = r0; bl[2*p][1] = r1; bl[2*p+1][0] = r2; bl[2*p+1][1] = r3;
            }
            #pragma unroll
            for (int mi = 0; mi < 4; mi++)
                #pragma unroll
                for (int ni = 0; ni < 4; ni++) {
                    mma_bf16(acc[mi][ni], ah[mi], bh[ni]);
                    mma_bf16(acc[mi][ni], ah[mi], bl[ni]);
                    mma_bf16(acc[mi][ni], al[mi], bh[ni]);
                }
        }
        __syncthreads();
    }

    const int qr = lane >> 2, qc = (lane & 3) * 2;

    if (!fuse) {
        #pragma unroll
        for (int mi = 0; mi < 4; mi++) {
            const int row = m0 + wm * 64 + mi * 16 + qr;
            #pragma unroll
            for (int ni = 0; ni < 4; ni++) {
                const int col = bn0 + wn * 32 + ni * 8 + qc;
                float b0 = bias ? bias[col]     : 0.f;
                float b1 = bias ? bias[col + 1] : 0.f;
                float2 v0 = make_float2(acc[mi][ni][0] + b0, acc[mi][ni][1] + b1);
                float2 v1 = make_float2(acc[mi][ni][2] + b0, acc[mi][ni][3] + b1);
                *(float2*)(C + (size_t)row * N + col)       = v0;
                *(float2*)(C + (size_t)(row + 8) * N + col) = v1;
            }
        }
        return;
    }

    // fused QKV epilogue
    float* st = (float*)smem;                      // [128][132]
    #pragma unroll
    for (int mi = 0; mi < 4; mi++) {
        const int r0r = wm * 64 + mi * 16 + qr;
        #pragma unroll
        for (int ni = 0; ni < 4; ni++) {
            const int c = wn * 32 + ni * 8 + qc;
            *(float2*)&st[(size_t)r0r * 132 + c] =
                make_float2(acc[mi][ni][0], acc[mi][ni][1]);
            *(float2*)&st[(size_t)(r0r + 8) * 132 + c] =
                make_float2(acc[mi][ni][2], acc[mi][ni][3]);
        }
    }
    __syncthreads();

    const int hIdx = blockIdx.x & 15;
    if (blockIdx.x < 32) {
        float* dstBase = (blockIdx.x < 16) ? outQ : outK;
        const int j = tid & 63;
        #pragma unroll 4
        for (int it = 0; it < 32; it++) {
            const int r = (tid >> 6) + it * 4;
            const int tg = m0 + r;
            const int bI = tg >> 11, t = tg & (LL - 1);
            float xe = st[(size_t)r * 132 + j];
            float xo = st[(size_t)r * 132 + 64 + j];
            float c = g_cos[t * 64 + j];
            float s = g_sin[t * 64 + j];
            float oe = xe * c - xo * s;
            float oo = xe * s + xo * c;
            oe = (oe > 0.f) ? (oe + 1.f) : expf(oe);
            oo = (oo > 0.f) ? (oo + 1.f) : expf(oo);
            float* dst = dstBase + ((size_t)(bI * HH + hIdx) * LL + t) * DD;
            dst[j]      = oe;
            dst[j + 64] = oo;
        }
    } else {
        const int d = tid & 127;
        #pragma unroll 4
        for (int it = 0; it < 64; it++) {
            const int r = (tid >> 7) + it * 2;
            const int tg = m0 + r;
            const int bI = tg >> 11, t = tg & (LL - 1);
            outV[((size_t)(bI * HH + hIdx) * LL + t) * DD + d] =
                st[(size_t)r * 132 + d];
        }
    }
}

// =====================================================================
// rope table
// =====================================================================
__global__ __launch_bounds__(256) void rope_table_kernel()
{
    int idx = blockIdx.x * 256 + threadIdx.x;
    if (idx >= LL * 64) return;
    int t = idx >> 6, j = idx & 63;
    float invf = (float)exp(-(double)j * 9.210340371976184 / 64.0);
    float ang = (float)t * invf;
    double sd, cd; sincos((double)ang, &sd, &cd);
    g_cos[idx] = (float)cd;
    g_sin[idx] = (float)sd;
}

// =====================================================================
// beta = clip(sigmoid(x @ Wg + bg), 0.8, 0.9995), stored [b*H+h][t]
// =====================================================================
__global__ __launch_bounds__(512) void beta_kernel(
    const float* __restrict__ x, const float* __restrict__ Wg,
    const float* __restrict__ bg, float* __restrict__ beta)
{
    __shared__ float row[HID];
    const int m = blockIdx.x;
    for (int i = threadIdx.x; i < HID; i += 512) row[i] = x[(size_t)m * HID + i];
    __syncthreads();
    const int w = threadIdx.x >> 5, lane = threadIdx.x & 31;
    float s = 0.f;
    for (int d = lane; d < HID; d += 32) s = fmaf(row[d], Wg[d * HH + w], s);
    #pragma unroll
    for (int o = 16; o; o >>= 1) s += __shfl_xor_sync(0xffffffffu, s, o);
    if (lane == 0) {
        s += bg[w];
        float bt = 1.f / (1.f + expf(-s));
        bt = fminf(fmaxf(bt, 0.8f), 0.9995f);
        const int b = m >> 11, t = m & (LL - 1);
        beta[(size_t)(b * HH + w) * LL + t] = bt;
    }
}

// =====================================================================
// chunk_kernel: per (bh, chunk), fully parallel.
// Computes decayed+masked A = QK^T, rsum, eLc, ksc -> gmem.
// grid = NBH*NCH = 1024, 256 threads.
// =====================================================================
#define CHUNK_SMEM ((128*68*2 + 64*68 + 2*64) * 4)

__global__ __launch_bounds__(256) void chunk_kernel(
    const float* __restrict__ gq, const float* __restrict__ gk,
    const float* __restrict__ gbeta)
{
    extern __shared__ float sm[];
    float* Qt = sm;                  // [128][68]
    float* Kt = Qt + 128*68;
    float* At = Kt + 128*68;         // [64][68] s-major
    float* bl = At + 64*68;          // [64]
    float* Lc = bl + 64;             // [64]

    const int tid  = threadIdx.x;
    const int bhch = blockIdx.x;
    const int bh   = bhch >> 5, ch = bhch & 31;
    const int t0   = ch * CHK;

    const float* qp = gq + (size_t)bh*LL*DD;
    const float* kp = gk + (size_t)bh*LL*DD;
    const float* bp = gbeta + (size_t)bh*LL;

    for (int idx = tid; idx < CHK*128; idx += 256) {
        const int i = idx >> 7, d = idx & 127;
        Qt[d*68 + i] = qp[(size_t)(t0+i)*DD + d];
        Kt[d*68 + i] = kp[(size_t)(t0+i)*DD + d];
    }
    if (tid < CHK) bl[tid] = logf(bp[t0+tid]);
    __syncthreads();
    if (tid == 0) {
        float a = 0.f;
        for (int i = 0; i < CHK; i++) { a += bl[i]; Lc[i] = a; }
    }
    __syncthreads();

    const int txA = tid & 15, tyA = tid >> 4;
    float accA[4][4];
    #pragma unroll
    for (int i=0;i<4;i++) { accA[i][0]=0;accA[i][1]=0;accA[i][2]=0;accA[i][3]=0; }
    for (int k = 0; k < 128; k++) {
        float4 qa = *(float4*)&Qt[k*68 + (tyA<<2)];
        float4 kb = *(float4*)&Kt[k*68 + (txA<<2)];
        const float qv[4] = {qa.x,qa.y,qa.z,qa.w};
        const float kv[4] = {kb.x,kb.y,kb.z,kb.w};
        #pragma unroll
        for (int i=0;i<4;i++)
            #pragma unroll
            for (int s=0;s<4;s++)
                accA[i][s] = fmaf(qv[i], kv[s], accA[i][s]);
    }
    if (tid < CHK) {
        g_eLc[(size_t)bhch*CHK + tid] = expf(Lc[tid]);
        g_ksc[(size_t)bhch*CHK + tid] = expf(Lc[CHK-1] - Lc[tid]);
    }
    // decay + causal mask -> smem + gmem
    #pragma unroll
    for (int ss=0; ss<4; ss++) {
        const int s = (txA<<2) + ss;
        float4 av;
        float* a4 = (float*)&av;
        #pragma unroll
        for (int ii=0; ii<4; ii++) {
            const int i = (tyA<<2) + ii;
            a4[ii] = (s <= i) ? accA[ii][ss]*expf(Lc[i]-Lc[s]) : 0.f;
        }
        *(float4*)&At[s*68 + (tyA<<2)] = av;
        *(float4*)&g_At[((size_t)bhch*CHK + s)*CHK + (tyA<<2)] = av;
    }
    __syncthreads();
    if (tid < CHK) {
        float s = 0.f;
        for (int sI = 0; sI < CHK; sI++) s += At[sI*68 + tid];
        g_rsum[(size_t)bhch*CHK + tid] = s;
    }
}

// =====================================================================
// state_kernel: sequential S/z propagation only. Stores per-chunk
// S_prev (DV slice) and z_prev (split 0) BEFORE each update.
// grid = NBH*NSPLIT = 128, 256 threads.
// =====================================================================
#define STATE_SMEM ((128*68 + 64*36 + 128*36 + 128 + 64 + 4) * 4)

__global__ __launch_bounds__(256) void state_kernel(
    const float* __restrict__ gk, const float* __restrict__ gv)
{
    extern __shared__ float sm[];
    float* Kt  = sm;                 // [128][68]
    float* Vs  = Kt  + 128*68;       // [64][36]
    float* Ssm = Vs  + 64*36;        // [128][36]
    float* z   = Ssm + 128*36;       // [128]
    float* ksc = z   + 128;          // [64]
    float* Gs  = ksc + 64;           // [1]

    const int tid   = threadIdx.x;
    const int bh    = blockIdx.x / NSPLIT;
    const int split = blockIdx.x % NSPLIT;

    const float* kp = gk + (size_t)bh*LL*DD;
    const float* vp = gv + (size_t)bh*LL*DD + split*DV;

    const int txO = tid & 7, tyO = tid >> 3;

    for (int i = tid; i < 128*36; i += 256) Ssm[i] = 0.f;
    if (tid < 128) z[tid] = 0.f;

    for (int ch = 0; ch < NCH; ch++) {
        const int t0 = ch * CHK;
        const int bhch = bh * NCH + ch;
        __syncthreads();
        for (int idx = tid; idx < CHK*128; idx += 256) {
            const int i = idx >> 7, d = idx & 127;
            Kt[d*68 + i] = kp[(size_t)(t0+i)*DD + d];
        }
        for (int idx = tid; idx < CHK*DV; idx += 256) {
            const int i = idx >> 5, e = idx & 31;
            Vs[i*36 + e] = vp[(size_t)(t0+i)*DD + e];
        }
        if (tid < CHK) ksc[tid] = g_ksc[(size_t)bhch*CHK + tid];
        if (tid == 0) Gs[0] = g_eLc[(size_t)bhch*CHK + CHK-1];
        __syncthreads();

        // store S_prev slice + z_prev for this chunk
        for (int f = tid; f < 128*8; f += 256) {
            const int d = f >> 3, eg = f & 7;
            *(float4*)&g_Sst[((size_t)bhch*DD + d)*DD + split*DV + eg*4] =
                *(float4*)&Ssm[d*36 + eg*4];
        }
        if (split == 0 && tid < 128)
            g_zst[(size_t)bhch*DD + tid] = z[tid];
        __syncthreads();

        const float G = Gs[0];
        {
            float accS[4][4];
            #pragma unroll
            for (int i=0;i<4;i++){accS[i][0]=0;accS[i][1]=0;accS[i][2]=0;accS[i][3]=0;}
            const int d0 = tyO << 2;
            for (int s = 0; s < CHK; s++) {
                const float sc = ksc[s];
                const float4 v4 = *(float4*)&Vs[s*36 + (txO<<2)];
                float kk[4];
                #pragma unroll
                for (int dd=0; dd<4; dd++) kk[dd] = Kt[(d0+dd)*68 + s] * sc;
                #pragma unroll
                for (int dd=0; dd<4; dd++) {
                    accS[dd][0]=fmaf(kk[dd],v4.x,accS[dd][0]);
                    accS[dd][1]=fmaf(kk[dd],v4.y,accS[dd][1]);
                    accS[dd][2]=fmaf(kk[dd],v4.z,accS[dd][2]);
                    accS[dd][3]=fmaf(kk[dd],v4.w,accS[dd][3]);
                }
            }
            #pragma unroll
            for (int dd=0; dd<4; dd++) {
                float4 sv = *(float4*)&Ssm[(d0+dd)*36 + (txO<<2)];
                sv.x = fmaf(G, sv.x, accS[dd][0]);
                sv.y = fmaf(G, sv.y, accS[dd][1]);
                sv.z = fmaf(G, sv.z, accS[dd][2]);
                sv.w = fmaf(G, sv.w, accS[dd][3]);
                *(float4*)&Ssm[(d0+dd)*36 + (txO<<2)] = sv;
            }
        }
        if (tid < 128) {
            float zv = z[tid] * G;
            for (int s = 0; s < CHK; s++) zv = fmaf(Kt[tid*68 + s], ksc[s], zv);
            z[tid] = zv;
        }
    }
}

// =====================================================================
// y_kernel: per (bh, chunk), fully parallel output.
// y = (A@V + eLc*(Q@S_prev)) / (rsum + eLc*(q.z_prev) + EPS),
// stored directly as bf16 hi/lo split into the Wo-GEMM input layout.
// grid = NBH*NCH = 1024, 256 threads.
// =====================================================================
#define Y_SMEM ((128*68 + 64*68 + 64*132 + 128*132 + 128 + 3*64) * 4)

__global__ __launch_bounds__(256) void y_kernel(
    const float* __restrict__ gq, const float* __restrict__ gv,
    __nv_bfloat16* __restrict__ yhi, __nv_bfloat16* __restrict__ ylo)
{
    extern __shared__ float sm[];
    float* Qt  = sm;                 // [128][68]
    float* At  = Qt  + 128*68;       // [64][68] s-major
    float* Vs  = At  + 64*68;        // [64][132]
    float* Ss  = Vs  + 64*132;       // [128][132]
    float* z   = Ss  + 128*132;      // [128]
    float* rsum= z   + 128;          // [64]
    float* eLc = rsum+ 64;           // [64]
    float* qz  = eLc + 64;           // [64]

    const int tid  = threadIdx.x;
    const int bhch = blockIdx.x;
    const int bh   = bhch >> 5, ch = bhch & 31;
    const int b    = bh >> 4, hd = bh & 15;
    const int t0   = ch * CHK;

    const float* qp = gq + (size_t)bh*LL*DD;
    const float* vp = gv + (size_t)bh*LL*DD;

    for (int idx = tid; idx < CHK*128; idx += 256) {
        const int i = idx >> 7, d = idx & 127;
        Qt[d*68 + i] = qp[(size_t)(t0+i)*DD + d];
    }
    for (int f = tid; f < 64*16; f += 256) {       // At: 64x64 as float4
        const int s = f >> 4, i0 = (f & 15) << 2;
        *(float4*)&At[s*68 + i0] =
            *(const float4*)&g_At[((size_t)bhch*CHK + s)*CHK + i0];
    }
    for (int f = tid; f < 64*32; f += 256) {       // V: 64x128 float4
        const int s = f >> 5, e4 = (f & 31) << 2;
        *(float4*)&Vs[s*132 + e4] = *(const float4*)&vp[(size_t)(t0+s)*DD + e4];
    }
    for (int f = tid; f < 128*32; f += 256) {      // S_prev: 128x128 float4
        const int d = f >> 5, e4 = (f & 31) << 2;
        *(float4*)&Ss[d*132 + e4] =
            *(const float4*)&g_Sst[((size_t)bhch*DD + d)*DD + e4];
    }
    if (tid < 128) z[tid] = g_zst[(size_t)bhch*DD + tid];
    if (tid < 64) {
        rsum[tid] = g_rsum[(size_t)bhch*CHK + tid];
        eLc[tid]  = g_eLc [(size_t)bhch*CHK + tid];
    }
    __syncthreads();

    if (tid < CHK) {
        float s = 0.f;
        for (int d = 0; d < 128; d++) s = fmaf(Qt[d*68 + tid], z[d], s);
        qz[tid] = s;
    }

    const int txO = tid & 31, tyO = tid >> 5;      // 8 i-rows x 4 e-cols each
    float oA[8][4], oI[8][4];
    #pragma unroll
    for (int r=0;r<8;r++)
        #pragma unroll
        for (int c=0;c<4;c++) { oA[r][c]=0.f; oI[r][c]=0.f; }

    for (int s = 0; s < CHK; s++) {
        const float4 v4 = *(float4*)&Vs[s*132 + (txO<<2)];
        #pragma unroll
        for (int r = 0; r < 8; r++) {
            const float a = At[s*68 + (tyO<<3) + r];
            oA[r][0]=fmaf(a,v4.x,oA[r][0]); oA[r][1]=fmaf(a,v4.y,oA[r][1]);
            oA[r][2]=fmaf(a,v4.z,oA[r][2]); oA[r][3]=fmaf(a,v4.w,oA[r][3]);
        }
    }
    for (int d = 0; d < 128; d++) {
        const float4 s4 = *(float4*)&Ss[d*132 + (txO<<2)];
        #pragma unroll
        for (int r = 0; r < 8; r++) {
            const float q = Qt[d*68 + (tyO<<3) + r];
            oI[r][0]=fmaf(q,s4.x,oI[r][0]); oI[r][1]=fmaf(q,s4.y,oI[r][1]);
            oI[r][2]=fmaf(q,s4.z,oI[r][2]); oI[r][3]=fmaf(q,s4.w,oI[r][3]);
        }
    }
    __syncthreads();

    #pragma unroll
    for (int r = 0; r < 8; r++) {
        const int i = (tyO<<3) + r;
        const float g = eLc[i];
        const float inv = 1.f / (rsum[i] + g*qz[i] + 1e-6f);
        float o[4];
        #pragma unroll
        for (int c = 0; c < 4; c++) o[c] = (oA[r][c] + g*oI[r][c]) * inv;
        __nv_bfloat16 hb[4], lb[4];
        #pragma unroll
        for (int u = 0; u < 4; u++) {
            hb[u] = __float2bfloat16(o[u]);
            lb[u] = __float2bfloat16(o[u] - __bfloat162float(hb[u]));
        }
        const size_t off = ((size_t)(b*LL + t0 + i))*HID + hd*DD + (txO<<2);
        __nv_bfloat162 ph0; ph0.x = hb[0]; ph0.y = hb[1];
        __nv_bfloat162 ph1; ph1.x = hb[2]; ph1.y = hb[3];
        __nv_bfloat162 pl0; pl0.x = lb[0]; pl0.y = lb[1];
        __nv_bfloat162 pl1; pl1.x = lb[2]; pl1.y = lb[3];
        *(__nv_bfloat162*)(yhi + off)     = ph0;
        *(__nv_bfloat162*)(yhi + off + 2) = ph1;
        *(__nv_bfloat162*)(ylo + off)     = pl0;
        *(__nv_bfloat162*)(ylo + off + 2) = pl1;
    }
}

// =====================================================================
// launch
// =====================================================================
extern "C" void kernel_launch(void* const* d_in, const int* in_sizes, int n_in,
                              void* d_out, int out_size)
{
    const float* x  = (const float*)d_in[0];
    const float* Wq = (const float*)d_in[1];
    const float* Wk = (const float*)d_in[2];
    const float* Wv = (const float*)d_in[3];
    const float* Wg = (const float*)d_in[4];
    const float* bg = (const float*)d_in[5];
    const float* Wo = (const float*)d_in[6];
    const float* bo = (const float*)d_in[7];
    float* out = (float*)d_out;

    float *q, *k, *v, *beta;
    __nv_bfloat16 *ahi, *alo, *whi, *wlo;
    cudaGetSymbolAddress((void**)&q,    g_q);
    cudaGetSymbolAddress((void**)&k,    g_k);
    cudaGetSymbolAddress((void**)&v,    g_v);
    cudaGetSymbolAddress((void**)&beta, g_beta);
    cudaGetSymbolAddress((void**)&ahi,  g_ahi);
    cudaGetSymbolAddress((void**)&alo,  g_alo);
    cudaGetSymbolAddress((void**)&whi,  g_whi);
    cudaGetSymbolAddress((void**)&wlo,  g_wlo);

    cudaFuncSetAttribute(gemm_tc_kernel,
        cudaFuncAttributeMaxDynamicSharedMemorySize, GEMM_SMEM);
    cudaFuncSetAttribute(chunk_kernel,
        cudaFuncAttributeMaxDynamicSharedMemorySize, CHUNK_SMEM);
    cudaFuncSetAttribute(state_kernel,
        cudaFuncAttributeMaxDynamicSharedMemorySize, STATE_SMEM);
    cudaFuncSetAttribute(y_kernel,
        cudaFuncAttributeMaxDynamicSharedMemorySize, Y_SMEM);

    const dim3 wgrid(HID/32, HID/32);        // (64, 64)
    const dim3 wblk(32, 8);
    const size_t WSZ = (size_t)HID*HID;

    rope_table_kernel<<<(LL*64 + 255)/256, 256>>>();
    cvt_split_kernel<<<(MM*HID/4 + 255)/256, 256>>>(
        (const float4*)x, ahi, alo, MM*HID/4);
    cvt_w_kernel<<<wgrid, wblk>>>(Wq, whi + 0*WSZ, wlo + 0*WSZ);
    cvt_w_kernel<<<wgrid, wblk>>>(Wk, whi + 1*WSZ, wlo + 1*WSZ);
    cvt_w_kernel<<<wgrid, wblk>>>(Wv, whi + 2*WSZ, wlo + 2*WSZ);

    // fused QKV projection + rope/phi/transpose epilogue
    gemm_tc_kernel<<<dim3(48, MM/128), 256, GEMM_SMEM>>>(
        ahi, alo, whi, wlo, nullptr, nullptr, q, k, v, 1, MM, 3*HID, HID);

    cvt_w_kernel<<<wgrid, wblk>>>(Wo, whi + 3*WSZ, wlo + 3*WSZ);
    beta_kernel<<<MM, 512>>>(x, Wg, bg, beta);

    // factored scan
    chunk_kernel<<<NBH*NCH, 256, CHUNK_SMEM>>>(q, k, beta);
    state_kernel<<<NBH*NSPLIT, 256, STATE_SMEM>>>(k, v);
    y_kernel<<<NBH*NCH, 256, Y_SMEM>>>(q, v, ahi, alo);

    // output projection
    gemm_tc_kernel<<<dim3(HID/128, MM/128), 256, GEMM_SMEM>>>(
        ahi, alo, whi + 3*WSZ, wlo + 3*WSZ, bo, out,
        nullptr, nullptr, nullptr, 0, MM, HID, HID);
}